// round 5
// baseline (speedup 1.0000x reference)
#include <cuda_runtime.h>
#include <math.h>

#define HH 512
#define WW 512
#define BB 16
#define NPIX (HH*WW)
#define NTOT (BB*NPIX)

#define F_A 0.955f
#define F_B 1.3693f
#define F_INF 1e6f
#define F_BIG 3.0e38f

// Scratch (device globals; no allocation allowed)
__device__ float  g_d[NTOT];          // distance grid / code grid
__device__ float  g_maxd[BB];         // per-sample max of final DT
__device__ int    g_hasfg[BB];
__device__ int    g_hasb[BB];
__device__ double g_acc[2 + 3*BB];    // [0]=focal, [1]=bnd, [2..]=inter,psum,tsum per sample

// ---------------------------------------------------------------------------
__global__ void zero_kernel() {
    int t = threadIdx.x;
    if (t < 2 + 3*BB) g_acc[t] = 0.0;
    if (t < BB) { g_hasfg[t] = 0; g_hasb[t] = 0; }
}

// ---------------------------------------------------------------------------
// Per-pixel: m = (target!=0); boundary = (in-bounds nb with m==1) && (in-bounds
// nb with m==0). Encodes code = boundary*2 + m into g_d; OR-reduces flags.
__global__ void __launch_bounds__(256) flags_kernel(const int* __restrict__ tgt) {
    int b = blockIdx.y;
    const int* T = tgt + b * NPIX;
    float* D = g_d + b * NPIX;
    int fg = 0, bd = 0;
    int start = blockIdx.x * 8192;
    for (int i = start + threadIdx.x; i < start + 8192; i += 256) {
        int y = i >> 9, x = i & 511;
        int any1 = 0, any0 = 0;
        #pragma unroll
        for (int dy = -1; dy <= 1; dy++) {
            int yy = y + dy;
            if ((unsigned)yy >= (unsigned)HH) continue;
            #pragma unroll
            for (int dx = -1; dx <= 1; dx++) {
                int xx = x + dx;
                if ((unsigned)xx >= (unsigned)WW) continue;
                int v = T[yy * WW + xx];
                any1 |= (v != 0);
                any0 |= (v == 0);
            }
        }
        int m = (T[i] != 0);
        int bound = any1 & any0;
        fg |= m; bd |= bound;
        D[i] = (float)((bound << 1) | m);
    }
    fg = __syncthreads_or(fg);
    bd = __syncthreads_or(bd);
    if (threadIdx.x == 0) {
        if (fg) atomicOr(&g_hasfg[b], 1);
        if (bd) atomicOr(&g_hasb[b], 1);
    }
}

// ---------------------------------------------------------------------------
// seeds = has_b ? boundary : (m < 0.5);  d = seed ? 0 : INF
__global__ void __launch_bounds__(256) seed_kernel() {
    int b = blockIdx.y;
    int hb = g_hasb[b];
    float* D = g_d + b * NPIX;
    int start = blockIdx.x * 4096;
    for (int i = start + threadIdx.x; i < start + 4096; i += 256) {
        int code = (int)D[i];
        int seed = hb ? (code >> 1) : ((code & 1) ^ 1);
        D[i] = seed ? 0.0f : F_INF;
    }
}

// ---------------------------------------------------------------------------
// Single-warp chamfer raster pass. 32 threads, 16 contiguous logical columns
// per thread. Previous row lives in registers; neighbor handoff via shfl.
// Bitwise-identical arithmetic to the reference:
//   v_j = m_j - A*j ; running-min(v) split as fmin(in-thread prefix,
//   exclusive cross-thread prefix of per-thread totals) ; cur_j = A*j + v.
// REV=true operates on the both-axes-flipped grid.
template<bool REV, bool DOMAX>
__global__ void __launch_bounds__(32, 1) chamfer_kernel() {
    const unsigned FULL = 0xffffffffu;
    int b = blockIdx.x;
    float* img = g_d + b * NPIX;
    const int lane = threadIdx.x;

    float prev[16], aj[16];
    #pragma unroll
    for (int k = 0; k < 16; k++) {
        prev[k] = F_INF;
        aj[k] = F_A * (float)(lane * 16 + k);
    }
    // physical column base of this lane's contiguous 16-col block
    const int colbase = REV ? (496 - lane * 16) : (lane * 16);
    float runmax = 0.0f;

    // prefetch first logical row
    float4 ld[4];
    {
        int pr = REV ? (HH - 1) : 0;
        const float4* p = (const float4*)(img + pr * WW + colbase);
        #pragma unroll
        for (int q = 0; q < 4; q++) ld[q] = p[q];
    }

    for (int r = 0; r < HH; r++) {
        float drow[16];
        #pragma unroll
        for (int q = 0; q < 4; q++) {
            float4 f = ld[q];
            if (!REV) {
                drow[q*4+0] = f.x; drow[q*4+1] = f.y;
                drow[q*4+2] = f.z; drow[q*4+3] = f.w;
            } else {  // physical idx d=q*4+i  ->  logical k = 15-d
                drow[15-(q*4+0)] = f.x; drow[15-(q*4+1)] = f.y;
                drow[15-(q*4+2)] = f.z; drow[15-(q*4+3)] = f.w;
            }
        }
        int pr = REV ? (HH - 1 - r) : r;
        if (r + 1 < HH) {  // prefetch next logical row (latency hidden by scan)
            int prn = REV ? (HH - 2 - r) : (r + 1);
            const float4* p = (const float4*)(img + prn * WW + colbase);
            #pragma unroll
            for (int q = 0; q < 4; q++) ld[q] = p[q];
        }

        // neighbor prev values across lanes
        float leftN  = __shfl_up_sync(FULL, prev[15], 1);
        float rightN = __shfl_down_sync(FULL, prev[0], 1);
        if (lane == 0)  leftN  = F_INF;
        if (lane == 31) rightN = F_INF;

        float v[16];
        #pragma unroll
        for (int k = 0; k < 16; k++) {
            float up = prev[k] + F_A;
            float ul = ((k == 0)  ? leftN  : prev[k-1]) + F_B;
            float ur = ((k == 15) ? rightN : prev[k+1]) + F_B;
            float m = fminf(fminf(drow[k], up), fminf(ul, ur));
            v[k] = m - aj[k];
        }

        // in-thread inclusive prefix min (serial; overlaps with scan below)
        float s[16];
        s[0] = v[0];
        #pragma unroll
        for (int k = 1; k < 16; k++) s[k] = fminf(s[k-1], v[k]);

        // thread total via tree (short chain feeding the warp scan)
        float t0[8], t1[4], t2[2], t;
        #pragma unroll
        for (int k = 0; k < 8; k++) t0[k] = fminf(v[2*k], v[2*k+1]);
        #pragma unroll
        for (int k = 0; k < 4; k++) t1[k] = fminf(t0[2*k], t0[2*k+1]);
        t2[0] = fminf(t1[0], t1[1]);
        t2[1] = fminf(t1[2], t1[3]);
        t = fminf(t2[0], t2[1]);

        // exclusive warp min-scan over thread totals
        float x = __shfl_up_sync(FULL, t, 1);
        if (lane == 0) x = F_BIG;
        #pragma unroll
        for (int o = 1; o < 32; o <<= 1) {
            float n = __shfl_up_sync(FULL, x, o);
            if (lane >= o) x = fminf(x, n);
        }

        float cur[16];
        #pragma unroll
        for (int k = 0; k < 16; k++) cur[k] = aj[k] + fminf(s[k], x);

        // store row (physical layout)
        {
            float4* op = (float4*)(img + pr * WW + colbase);
            #pragma unroll
            for (int q = 0; q < 4; q++) {
                float4 f;
                if (!REV) {
                    f.x = cur[q*4+0]; f.y = cur[q*4+1];
                    f.z = cur[q*4+2]; f.w = cur[q*4+3];
                } else {
                    f.x = cur[15-(q*4+0)]; f.y = cur[15-(q*4+1)];
                    f.z = cur[15-(q*4+2)]; f.w = cur[15-(q*4+3)];
                }
                op[q] = f;
            }
        }

        if (DOMAX) {
            float m0[8], m1[4], m2[2];
            #pragma unroll
            for (int k = 0; k < 8; k++) m0[k] = fmaxf(cur[2*k], cur[2*k+1]);
            #pragma unroll
            for (int k = 0; k < 4; k++) m1[k] = fmaxf(m0[2*k], m0[2*k+1]);
            m2[0] = fmaxf(m1[0], m1[1]);
            m2[1] = fmaxf(m1[2], m1[3]);
            runmax = fmaxf(runmax, fmaxf(m2[0], m2[1]));
        }

        #pragma unroll
        for (int k = 0; k < 16; k++) prev[k] = cur[k];
    }

    if (DOMAX) {
        #pragma unroll
        for (int o = 16; o > 0; o >>= 1)
            runmax = fmaxf(runmax, __shfl_xor_sync(FULL, runmax, o));
        if (lane == 0) g_maxd[b] = runmax;
    }
}

// ---------------------------------------------------------------------------
// Fused loss: focal, boundary (normalized dist), per-sample dice/iou sums.
__global__ void __launch_bounds__(256) loss_kernel(const float* __restrict__ pred,
                                                   const int* __restrict__ tgt) {
    int b = blockIdx.y;
    int base = b * NPIX + blockIdx.x * 4096;
    float mx = g_maxd[b];
    float scale = (mx > 0.0f) ? (1.0f / fmaxf(mx, 1e-12f)) : 1.0f;
    int hasfg = g_hasfg[b];

    float a_f = 0.0f, a_b = 0.0f, a_i = 0.0f, a_p = 0.0f, a_t = 0.0f;
    #pragma unroll 4
    for (int k = 0; k < 16; k++) {
        int gi = base + threadIdx.x + k * 256;
        float x = pred[gi];
        float t = (tgt[gi] != 0) ? 1.0f : 0.0f;
        float e = expf(-fabsf(x));
        float l1p = log1pf(e);
        float s = 1.0f / (1.0f + e);
        float p = (x >= 0.0f) ? s : 1.0f - s;          // sigmoid(x)
        float ls_x  = fminf(x, 0.0f)  - l1p;           // log sigmoid(x)
        float ls_nx = fminf(-x, 0.0f) - l1p;           // log sigmoid(-x)
        float bce = -(t * ls_x + (1.0f - t) * ls_nx);
        float pt = t * p + (1.0f - t) * (1.0f - p);
        float at = (t == 1.0f) ? 0.25f : 0.75f;
        float om = 1.0f - pt;
        a_f += at * om * om * bce;
        float dn = hasfg ? (g_d[gi] * scale) : 1.0f;
        a_b += (t * (1.0f - p) + (1.0f - t) * p) * (1.0f + dn);
        a_i += p * t;
        a_p += p;
        a_t += t;
    }

    #pragma unroll
    for (int o = 16; o > 0; o >>= 1) {
        a_f += __shfl_down_sync(0xffffffffu, a_f, o);
        a_b += __shfl_down_sync(0xffffffffu, a_b, o);
        a_i += __shfl_down_sync(0xffffffffu, a_i, o);
        a_p += __shfl_down_sync(0xffffffffu, a_p, o);
        a_t += __shfl_down_sync(0xffffffffu, a_t, o);
    }
    __shared__ float red[8][5];
    int lane = threadIdx.x & 31, wid = threadIdx.x >> 5;
    if (lane == 0) {
        red[wid][0] = a_f; red[wid][1] = a_b; red[wid][2] = a_i;
        red[wid][3] = a_p; red[wid][4] = a_t;
    }
    __syncthreads();
    if (threadIdx.x == 0) {
        float s0 = 0, s1 = 0, s2 = 0, s3 = 0, s4 = 0;
        #pragma unroll
        for (int w = 0; w < 8; w++) {
            s0 += red[w][0]; s1 += red[w][1]; s2 += red[w][2];
            s3 += red[w][3]; s4 += red[w][4];
        }
        atomicAdd(&g_acc[0], (double)s0);
        atomicAdd(&g_acc[1], (double)s1);
        atomicAdd(&g_acc[2 + b], (double)s2);
        atomicAdd(&g_acc[2 + BB + b], (double)s3);
        atomicAdd(&g_acc[2 + 2*BB + b], (double)s4);
    }
}

// ---------------------------------------------------------------------------
__global__ void finalize_kernel(const float* __restrict__ lv, float* __restrict__ out) {
    if (threadIdx.x == 0) {
        double N = (double)NTOT;
        double focal = g_acc[0] / N;
        double bnd   = g_acc[1] / N;
        double dsum = 0.0, isum = 0.0;
        for (int b = 0; b < BB; b++) {
            double inter = g_acc[2 + b];
            double ps = g_acc[2 + BB + b];
            double ts = g_acc[2 + 2*BB + b];
            double tot = ps + ts;
            dsum += (2.0 * inter + 1e-6) / (tot + 1e-6);
            isum += (inter + 1e-6) / (tot - inter + 1e-6);
        }
        double dice = 1.0 - dsum / (double)BB;
        double iou  = 1.0 - isum / (double)BB;
        float f = (float)focal, d = (float)dice, bb = (float)bnd, io = (float)iou;
        float total = expf(-lv[0]) * f + lv[0]
                    + expf(-lv[1]) * d + lv[1]
                    + expf(-lv[2]) * bb + lv[2]
                    + expf(-lv[3]) * io + lv[3];
        out[0] = total;
        out[1] = f;
        out[2] = d;
        out[3] = bb;
        out[4] = io;
    }
}

// ---------------------------------------------------------------------------
extern "C" void kernel_launch(void* const* d_in, const int* in_sizes, int n_in,
                              void* d_out, int out_size) {
    const float* pred = (const float*)d_in[0];
    const int*   tgt  = (const int*)d_in[1];
    const float* lv   = (const float*)d_in[2];
    float* out = (float*)d_out;

    zero_kernel<<<1, 64>>>();
    flags_kernel<<<dim3(32, BB), 256>>>(tgt);
    seed_kernel<<<dim3(64, BB), 256>>>();
    chamfer_kernel<false, false><<<BB, 32>>>();
    chamfer_kernel<true,  true ><<<BB, 32>>>();
    loss_kernel<<<dim3(64, BB), 256>>>(pred, tgt);
    finalize_kernel<<<1, 32>>>(lv, out);
}

// round 6
// speedup vs baseline: 8.7877x; 8.7877x over previous
#include <cuda_runtime.h>
#include <math.h>

#define HH 512
#define WW 512
#define BB 16
#define NPIX (HH*WW)
#define NTOT (BB*NPIX)
#define WPR 16            // 32-bit words per row
#define WPS (HH*WPR)      // words per sample bitmap = 8192

#define F_A  0.955f
#define F_B  1.3693f
#define BA_C (1.3693f - 0.955f)
#define F_INF 1e6f

// Scratch (device globals; no allocation allowed)
__device__ float    g_d[NTOT];           // distance map
__device__ unsigned g_mbits[BB*WPS];     // mask bitmap
__device__ unsigned g_bbits[BB*WPS];     // boundary bitmap
__device__ unsigned g_sbits[BB*WPS];     // seed bitmap
__device__ int      g_maxdi[BB];         // per-sample max dist (float bits, >=0)
__device__ int      g_hasfg[BB];
__device__ int      g_hasb[BB];
__device__ int      g_hasseed[BB];
__device__ double   g_acc[2 + 3*BB];

// ---------------------------------------------------------------------------
__global__ void zero_kernel() {
    int t = threadIdx.x;
    if (t < 2 + 3*BB) g_acc[t] = 0.0;
    if (t < BB) { g_hasfg[t] = 0; g_hasb[t] = 0; g_hasseed[t] = 0; g_maxdi[t] = 0; }
}

// ---------------------------------------------------------------------------
// Pack target into bitmap: bit j of word wi (row r) = (target[r][wi*32+j] != 0)
__global__ void __launch_bounds__(256) pack_kernel(const int* __restrict__ tgt) {
    int b = blockIdx.y;
    int widx = blockIdx.x * 256 + threadIdx.x;      // word index within sample
    const int4* T = (const int4*)(tgt + b * NPIX + widx * 32);
    unsigned w = 0;
    #pragma unroll
    for (int q = 0; q < 8; q++) {
        int4 v = T[q];
        w |= (v.x != 0 ? 1u : 0u) << (q*4 + 0);
        w |= (v.y != 0 ? 1u : 0u) << (q*4 + 1);
        w |= (v.z != 0 ? 1u : 0u) << (q*4 + 2);
        w |= (v.w != 0 ? 1u : 0u) << (q*4 + 3);
    }
    // wait: that packs 32 ints as 8 groups of 4 consecutive -> bit order OK:
    // element e = q*4 + i maps to bit q*4+i. Correct.
    g_mbits[b * WPS + widx] = w;
}

// ---------------------------------------------------------------------------
// Bitwise morphological boundary: pixel is boundary iff its in-bounds 3x3
// neighborhood (incl self) contains both a 1 and a 0. Out-of-bounds votes 0.
__global__ void __launch_bounds__(256) bound_kernel() {
    int b = blockIdx.y;
    int widx = blockIdx.x * 256 + threadIdx.x;
    int r = widx >> 4, wi = widx & 15;
    const unsigned* M = g_mbits + b * WPS;

    unsigned any1 = 0, any0 = 0;
    #pragma unroll
    for (int dr = -1; dr <= 1; dr++) {
        int r2 = r + dr;
        if ((unsigned)r2 >= (unsigned)HH) continue;
        unsigned c = M[r2 * WPR + wi];
        unsigned l = (wi > 0)  ? M[r2 * WPR + wi - 1] : 0u;
        unsigned rt = (wi < 15) ? M[r2 * WPR + wi + 1] : 0u;
        any1 |= c | (c << 1) | (l >> 31) | (c >> 1) | (rt << 31);
        unsigned cn = ~c;
        unsigned ln = (wi > 0)  ? ~l  : 0u;   // outside image contributes nothing
        unsigned rn = (wi < 15) ? ~rt : 0u;
        any0 |= cn | (cn << 1) | (ln >> 31) | (cn >> 1) | (rn << 31);
    }
    unsigned bw = any1 & any0;
    g_bbits[b * WPS + widx] = bw;

    int fg = (M[widx] != 0u);
    int bd = (bw != 0u);
    fg = __syncthreads_or(fg);
    bd = __syncthreads_or(bd);
    if (threadIdx.x == 0) {
        if (fg) atomicOr(&g_hasfg[b], 1);
        if (bd) atomicOr(&g_hasb[b], 1);
    }
}

// ---------------------------------------------------------------------------
// seeds = has_b ? boundary : ~mask (all 512 bits per row valid)
__global__ void __launch_bounds__(256) seedsel_kernel() {
    int b = blockIdx.y;
    int widx = blockIdx.x * 256 + threadIdx.x;
    int hb = g_hasb[b];
    unsigned s = hb ? g_bbits[b * WPS + widx] : ~g_mbits[b * WPS + widx];
    g_sbits[b * WPS + widx] = s;
    int hs = __syncthreads_or(s != 0u);
    if (threadIdx.x == 0 && hs) atomicOr(&g_hasseed[b], 1);
}

// ---------------------------------------------------------------------------
// Distance (in columns) from x to nearest set bit in a 512-bit row.
// Stops scanning words once no closer hit than min(found, cap) is possible.
__device__ __forceinline__ int nearest_bit(const unsigned* __restrict__ rw, int x, int cap) {
    int wi = x >> 5, bi = x & 31;
    unsigned w = rw[wi];
    int d = 1 << 29;
    unsigned lm = w << (31 - bi);               // bits <= bi
    if (lm) d = __clz(lm);
    unsigned rm = w >> bi;                      // bits >= bi
    if (rm) d = min(d, __ffs(rm) - 1);
    #pragma unroll 1
    for (int k = 1; k < WPR; k++) {
        int lwi = wi - k, rwi = wi + k;
        int dl = (lwi >= 0)  ? (bi + 32*k - 31) : (1 << 29);  // best possible from left word
        int dr = (rwi < WPR) ? (32*k - bi)      : (1 << 29);  // best possible from right word
        int dmin = min(dl, dr);
        if (dmin >= min(d, cap)) break;
        if (lwi >= 0) {
            unsigned lw = rw[lwi];
            if (lw) d = min(d, bi + 32*k - 31 + __clz(lw));
        }
        if (rwi < WPR) {
            unsigned rw2 = rw[rwi];
            if (rw2) d = min(d, 32*k - bi + __ffs(rw2) - 1);
        }
    }
    return d;
}

// ---------------------------------------------------------------------------
// Closed-form chamfer DT: d(p) = min over seeds of a*max(|dx|,|dy|)+(b-a)*min.
// Seed bitmap in shared; expand |dy| with early break (a*dy >= best).
__global__ void __launch_bounds__(256) dt_kernel() {
    int b = blockIdx.y;
    __shared__ unsigned sb[WPS];
    const unsigned* src = g_sbits + b * WPS;
    for (int i = threadIdx.x; i < WPS; i += 256) sb[i] = src[i];
    __syncthreads();

    int hs = g_hasseed[b];
    int r0 = blockIdx.x * 8;
    float lmax = 0.0f;

    for (int rr = 0; rr < 8; rr++) {
        int y = r0 + rr;
        #pragma unroll
        for (int cc = 0; cc < 2; cc++) {
            int x = threadIdx.x + cc * 256;
            float best = F_INF;
            if (hs) {
                int nd = nearest_bit(sb + y * WPR, x, 600);
                if (nd < (1 << 28)) best = F_A * (float)nd;
                #pragma unroll 1
                for (int dy = 1; dy < HH; dy++) {
                    float ady = F_A * (float)dy;
                    if (ady >= best) break;
                    // prune word scan: far branch a*nd+ba*dy, near branch a*dy+ba*nd
                    float capf = fmaxf((best - BA_C * (float)dy) * (1.0f / F_A),
                                       fminf((float)dy, (best - ady) * (1.0f / BA_C))) + 1.0f;
                    int cap = (int)fminf(capf, 600.0f);
                    int yu = y - dy;
                    if (yu >= 0) {
                        int nd2 = nearest_bit(sb + yu * WPR, x, cap);
                        if (nd2 < (1 << 28)) {
                            float f = (nd2 >= dy) ? (F_A * (float)nd2 + BA_C * (float)dy)
                                                  : (ady + BA_C * (float)nd2);
                            best = fminf(best, f);
                        }
                    }
                    int yd = y + dy;
                    if (yd < HH) {
                        int nd2 = nearest_bit(sb + yd * WPR, x, cap);
                        if (nd2 < (1 << 28)) {
                            float f = (nd2 >= dy) ? (F_A * (float)nd2 + BA_C * (float)dy)
                                                  : (ady + BA_C * (float)nd2);
                            best = fminf(best, f);
                        }
                    }
                }
            }
            g_d[b * NPIX + y * WW + x] = best;
            lmax = fmaxf(lmax, best);
        }
    }

    // block max -> atomicMax (float bits valid for non-negative values)
    #pragma unroll
    for (int o = 16; o > 0; o >>= 1)
        lmax = fmaxf(lmax, __shfl_xor_sync(0xffffffffu, lmax, o));
    __shared__ float wm[8];
    int lane = threadIdx.x & 31, wid = threadIdx.x >> 5;
    if (lane == 0) wm[wid] = lmax;
    __syncthreads();
    if (threadIdx.x == 0) {
        float m = wm[0];
        #pragma unroll
        for (int w = 1; w < 8; w++) m = fmaxf(m, wm[w]);
        atomicMax(&g_maxdi[b], __float_as_int(m));
    }
}

// ---------------------------------------------------------------------------
// Fused loss: focal, boundary (normalized dist), per-sample dice/iou sums.
__global__ void __launch_bounds__(256) loss_kernel(const float* __restrict__ pred,
                                                   const int* __restrict__ tgt) {
    int b = blockIdx.y;
    int base = b * NPIX + blockIdx.x * 4096;
    float mx = __int_as_float(g_maxdi[b]);
    float scale = (mx > 0.0f) ? (1.0f / fmaxf(mx, 1e-12f)) : 1.0f;
    int hasfg = g_hasfg[b];

    float a_f = 0.0f, a_b = 0.0f, a_i = 0.0f, a_p = 0.0f, a_t = 0.0f;
    #pragma unroll 4
    for (int k = 0; k < 16; k++) {
        int gi = base + threadIdx.x + k * 256;
        float x = pred[gi];
        float t = (tgt[gi] != 0) ? 1.0f : 0.0f;
        float e = expf(-fabsf(x));
        float l1p = log1pf(e);
        float s = 1.0f / (1.0f + e);
        float p = (x >= 0.0f) ? s : 1.0f - s;          // sigmoid(x)
        float ls_x  = fminf(x, 0.0f)  - l1p;           // log sigmoid(x)
        float ls_nx = fminf(-x, 0.0f) - l1p;           // log sigmoid(-x)
        float bce = -(t * ls_x + (1.0f - t) * ls_nx);
        float pt = t * p + (1.0f - t) * (1.0f - p);
        float at = (t == 1.0f) ? 0.25f : 0.75f;
        float om = 1.0f - pt;
        a_f += at * om * om * bce;
        float dn = hasfg ? (g_d[gi] * scale) : 1.0f;
        a_b += (t * (1.0f - p) + (1.0f - t) * p) * (1.0f + dn);
        a_i += p * t;
        a_p += p;
        a_t += t;
    }

    #pragma unroll
    for (int o = 16; o > 0; o >>= 1) {
        a_f += __shfl_down_sync(0xffffffffu, a_f, o);
        a_b += __shfl_down_sync(0xffffffffu, a_b, o);
        a_i += __shfl_down_sync(0xffffffffu, a_i, o);
        a_p += __shfl_down_sync(0xffffffffu, a_p, o);
        a_t += __shfl_down_sync(0xffffffffu, a_t, o);
    }
    __shared__ float red[8][5];
    int lane = threadIdx.x & 31, wid = threadIdx.x >> 5;
    if (lane == 0) {
        red[wid][0] = a_f; red[wid][1] = a_b; red[wid][2] = a_i;
        red[wid][3] = a_p; red[wid][4] = a_t;
    }
    __syncthreads();
    if (threadIdx.x == 0) {
        float s0 = 0, s1 = 0, s2 = 0, s3 = 0, s4 = 0;
        #pragma unroll
        for (int w = 0; w < 8; w++) {
            s0 += red[w][0]; s1 += red[w][1]; s2 += red[w][2];
            s3 += red[w][3]; s4 += red[w][4];
        }
        atomicAdd(&g_acc[0], (double)s0);
        atomicAdd(&g_acc[1], (double)s1);
        atomicAdd(&g_acc[2 + b], (double)s2);
        atomicAdd(&g_acc[2 + BB + b], (double)s3);
        atomicAdd(&g_acc[2 + 2*BB + b], (double)s4);
    }
}

// ---------------------------------------------------------------------------
__global__ void finalize_kernel(const float* __restrict__ lv, float* __restrict__ out) {
    if (threadIdx.x == 0) {
        double N = (double)NTOT;
        double focal = g_acc[0] / N;
        double bnd   = g_acc[1] / N;
        double dsum = 0.0, isum = 0.0;
        for (int b = 0; b < BB; b++) {
            double inter = g_acc[2 + b];
            double ps = g_acc[2 + BB + b];
            double ts = g_acc[2 + 2*BB + b];
            double tot = ps + ts;
            dsum += (2.0 * inter + 1e-6) / (tot + 1e-6);
            isum += (inter + 1e-6) / (tot - inter + 1e-6);
        }
        double dice = 1.0 - dsum / (double)BB;
        double iou  = 1.0 - isum / (double)BB;
        float f = (float)focal, d = (float)dice, bb = (float)bnd, io = (float)iou;
        float total = expf(-lv[0]) * f + lv[0]
                    + expf(-lv[1]) * d + lv[1]
                    + expf(-lv[2]) * bb + lv[2]
                    + expf(-lv[3]) * io + lv[3];
        out[0] = total;
        out[1] = f;
        out[2] = d;
        out[3] = bb;
        out[4] = io;
    }
}

// ---------------------------------------------------------------------------
extern "C" void kernel_launch(void* const* d_in, const int* in_sizes, int n_in,
                              void* d_out, int out_size) {
    const float* pred = (const float*)d_in[0];
    const int*   tgt  = (const int*)d_in[1];
    const float* lv   = (const float*)d_in[2];
    float* out = (float*)d_out;

    zero_kernel<<<1, 64>>>();
    pack_kernel<<<dim3(32, BB), 256>>>(tgt);
    bound_kernel<<<dim3(32, BB), 256>>>();
    seedsel_kernel<<<dim3(32, BB), 256>>>();
    dt_kernel<<<dim3(64, BB), 256>>>();
    loss_kernel<<<dim3(64, BB), 256>>>(pred, tgt);
    finalize_kernel<<<1, 32>>>(lv, out);
}

// round 7
// speedup vs baseline: 10.0725x; 1.1462x over previous
#include <cuda_runtime.h>
#include <math.h>

#define HH 512
#define WW 512
#define BB 16
#define NPIX (HH*WW)
#define NTOT (BB*NPIX)
#define WPR 16            // 32-bit words per row
#define WPS (HH*WPR)      // words per sample bitmap = 8192

#define F_A  0.955f
#define F_B  1.3693f
#define BA_C (1.3693f - 0.955f)
#define F_INF 1e6f

// acc layout: [0]=focal ; [1..16]=w0 ; [17..32]=w0*d ; [33..48]=inter ;
//             [49..64]=psum ; [65..80]=tsum
#define ACC_N 81
#define A_W0   1
#define A_W0D  17
#define A_I    33
#define A_P    49
#define A_T    65

// Scratch (device globals; no allocation allowed)
__device__ unsigned g_mbits[BB*WPS];     // mask bitmap
__device__ unsigned g_bbits[BB*WPS];     // boundary bitmap
__device__ int      g_maxdi[BB];         // per-sample max dist (float bits, >=0)
__device__ int      g_hasfg[BB];
__device__ int      g_hasb[BB];
__device__ int      g_anyzero[BB];
__device__ double   g_acc[ACC_N];

// ---------------------------------------------------------------------------
__global__ void zero_kernel() {
    int t = threadIdx.x;
    if (t < ACC_N) g_acc[t] = 0.0;
    if (t < BB) { g_hasfg[t] = 0; g_hasb[t] = 0; g_anyzero[t] = 0; g_maxdi[t] = 0; }
}

// ---------------------------------------------------------------------------
// Fused pack + boundary. Each block: sample b, 32 rows. Packs a 34-row halo
// slab of the target into shared bitmap, then computes the bitwise
// morphological boundary (pixel is boundary iff in-bounds 3x3 neighborhood,
// incl. self, contains both a 1 and a 0; out-of-bounds contributes nothing).
// Writes mask + boundary bitmaps and per-sample flags.
__global__ void __launch_bounds__(256) packbound_kernel(const int* __restrict__ tgt) {
    int b = blockIdx.y;
    int r0 = blockIdx.x * 32;
    __shared__ unsigned pm[34 * WPR];

    for (int w = threadIdx.x; w < 34 * WPR; w += 256) {
        int ri = w >> 4;              // 0..33  -> row r0-1+ri
        int wi = w & 15;
        int y = r0 - 1 + ri;
        unsigned word = 0;
        if ((unsigned)y < (unsigned)HH) {
            const int4* T = (const int4*)(tgt + b * NPIX + y * WW + wi * 32);
            #pragma unroll
            for (int q = 0; q < 8; q++) {
                int4 v = T[q];
                word |= (v.x != 0 ? 1u : 0u) << (q*4 + 0);
                word |= (v.y != 0 ? 1u : 0u) << (q*4 + 1);
                word |= (v.z != 0 ? 1u : 0u) << (q*4 + 2);
                word |= (v.w != 0 ? 1u : 0u) << (q*4 + 3);
            }
        }
        pm[w] = word;
    }
    __syncthreads();

    int fg = 0, bd = 0, az = 0;
    #pragma unroll 1
    for (int w = threadIdx.x; w < 32 * WPR; w += 256) {
        int lr = (w >> 4) + 1;        // local row 1..32
        int wi = w & 15;
        int y = r0 + (w >> 4);
        unsigned any1 = 0, any0 = 0;
        #pragma unroll
        for (int dr = -1; dr <= 1; dr++) {
            int y2 = y + dr;
            if ((unsigned)y2 >= (unsigned)HH) continue;
            int l2 = lr + dr;
            unsigned c  = pm[l2 * WPR + wi];
            unsigned lw = (wi > 0)  ? pm[l2 * WPR + wi - 1] : 0u;
            unsigned rw = (wi < 15) ? pm[l2 * WPR + wi + 1] : 0u;
            any1 |= c | (c << 1) | (lw >> 31) | (c >> 1) | (rw << 31);
            unsigned cn = ~c;
            unsigned ln = (wi > 0)  ? ~lw : 0u;   // outside image votes nothing
            unsigned rn = (wi < 15) ? ~rw : 0u;
            any0 |= cn | (cn << 1) | (ln >> 31) | (cn >> 1) | (rn << 31);
        }
        unsigned bw = any1 & any0;
        unsigned mw = pm[lr * WPR + wi];
        g_bbits[b * WPS + y * WPR + wi] = bw;
        g_mbits[b * WPS + y * WPR + wi] = mw;
        fg |= (mw != 0u);
        bd |= (bw != 0u);
        az |= (mw != 0xffffffffu);
    }
    fg = __syncthreads_or(fg);
    bd = __syncthreads_or(bd);
    az = __syncthreads_or(az);
    if (threadIdx.x == 0) {
        if (fg) atomicOr(&g_hasfg[b], 1);
        if (bd) atomicOr(&g_hasb[b], 1);
        if (az) atomicOr(&g_anyzero[b], 1);
    }
}

// ---------------------------------------------------------------------------
// Distance (in columns) from x to nearest set bit in a 512-bit row.
// Stops scanning words once no closer hit than min(found, cap) is possible.
__device__ __forceinline__ int nearest_bit(const unsigned* __restrict__ rw, int x, int cap) {
    int wi = x >> 5, bi = x & 31;
    unsigned w = rw[wi];
    int d = 1 << 29;
    unsigned lm = w << (31 - bi);               // bits <= bi
    if (lm) d = __clz(lm);
    unsigned rm = w >> bi;                      // bits >= bi
    if (rm) d = min(d, __ffs(rm) - 1);
    #pragma unroll 1
    for (int k = 1; k < WPR; k++) {
        int lwi = wi - k, rwi = wi + k;
        int dl = (lwi >= 0)  ? (bi + 32*k - 31) : (1 << 29);
        int dr = (rwi < WPR) ? (32*k - bi)      : (1 << 29);
        if (min(dl, dr) >= min(d, cap)) break;
        if (lwi >= 0) {
            unsigned lw = rw[lwi];
            if (lw) d = min(d, bi + 32*k - 31 + __clz(lw));
        }
        if (rwi < WPR) {
            unsigned rw2 = rw[rwi];
            if (rw2) d = min(d, 32*k - bi + __ffs(rw2) - 1);
        }
    }
    return d;
}

// ---------------------------------------------------------------------------
// Fused closed-form chamfer DT + loss. Each block: 16 rows of one sample.
// d(p) = min over seeds of a*max(|dx|,|dy|)+(b-a)*min(|dx|,|dy|), computed in
// registers and consumed immediately. Boundary term kept separable:
// sum(w0) and sum(w0*d); normalization by the sample max happens in finalize.
__global__ void __launch_bounds__(256) dtloss_kernel(const float* __restrict__ pred) {
    int b = blockIdx.y;
    __shared__ unsigned sb[WPS];   // 32KB seed bitmap
    int hb = g_hasb[b];
    const unsigned* bs = g_bbits + b * WPS;
    const unsigned* ms = g_mbits + b * WPS;
    for (int i = threadIdx.x; i < WPS; i += 256)
        sb[i] = hb ? bs[i] : ~ms[i];
    __syncthreads();

    int hs = hb ? 1 : g_anyzero[b];
    int r0 = blockIdx.x * 16;
    float lmax = 0.0f;
    float a_f = 0.f, a_w0 = 0.f, a_w0d = 0.f, a_i = 0.f, a_p = 0.f, a_t = 0.f;

    #pragma unroll 1
    for (int rr = 0; rr < 16; rr++) {
        int y = r0 + rr;
        #pragma unroll
        for (int cc = 0; cc < 2; cc++) {
            int x = threadIdx.x + cc * 256;
            float best = F_INF;
            if (hs) {
                int nd = nearest_bit(sb + y * WPR, x, 600);
                if (nd < (1 << 28)) best = F_A * (float)nd;
                #pragma unroll 1
                for (int dy = 1; dy < HH; dy++) {
                    float ady = F_A * (float)dy;
                    if (ady >= best) break;
                    float capf = fmaxf((best - BA_C * (float)dy) * (1.0f / F_A),
                                       fminf((float)dy, (best - ady) * (1.0f / BA_C))) + 1.0f;
                    int cap = (int)fminf(capf, 600.0f);
                    int yu = y - dy;
                    if (yu >= 0) {
                        int nd2 = nearest_bit(sb + yu * WPR, x, cap);
                        if (nd2 < (1 << 28)) {
                            float f = (nd2 >= dy) ? (F_A * (float)nd2 + BA_C * (float)dy)
                                                  : (ady + BA_C * (float)nd2);
                            best = fminf(best, f);
                        }
                    }
                    int yd = y + dy;
                    if (yd < HH) {
                        int nd2 = nearest_bit(sb + yd * WPR, x, cap);
                        if (nd2 < (1 << 28)) {
                            float f = (nd2 >= dy) ? (F_A * (float)nd2 + BA_C * (float)dy)
                                                  : (ady + BA_C * (float)nd2);
                            best = fminf(best, f);
                        }
                    }
                }
            }
            lmax = fmaxf(lmax, best);

            // ---- loss terms for this pixel ----
            int gi = b * NPIX + y * WW + x;
            float xv = pred[gi];
            float t = (float)((ms[y * WPR + (x >> 5)] >> (x & 31)) & 1u);
            float e = __expf(-fabsf(xv));
            float l1p = __logf(1.0f + e);
            float s = __fdividef(1.0f, 1.0f + e);
            float p = (xv >= 0.0f) ? s : 1.0f - s;            // sigmoid
            float ls_x  = fminf(xv, 0.0f)  - l1p;             // log sigmoid(x)
            float ls_nx = fminf(-xv, 0.0f) - l1p;             // log sigmoid(-x)
            float bce = -(t * ls_x + (1.0f - t) * ls_nx);
            float pt = t * p + (1.0f - t) * (1.0f - p);
            float at = (t == 1.0f) ? 0.25f : 0.75f;
            float om = 1.0f - pt;
            a_f += at * om * om * bce;
            float w0 = t * (1.0f - p) + (1.0f - t) * p;
            a_w0  += w0;
            a_w0d += w0 * best;
            a_i += p * t;
            a_p += p;
            a_t += t;
        }
    }

    // block reduce 6 sums + max
    #pragma unroll
    for (int o = 16; o > 0; o >>= 1) {
        a_f   += __shfl_down_sync(0xffffffffu, a_f,   o);
        a_w0  += __shfl_down_sync(0xffffffffu, a_w0,  o);
        a_w0d += __shfl_down_sync(0xffffffffu, a_w0d, o);
        a_i   += __shfl_down_sync(0xffffffffu, a_i,   o);
        a_p   += __shfl_down_sync(0xffffffffu, a_p,   o);
        a_t   += __shfl_down_sync(0xffffffffu, a_t,   o);
        lmax   = fmaxf(lmax, __shfl_down_sync(0xffffffffu, lmax, o));
    }
    __shared__ float red[8][7];
    int lane = threadIdx.x & 31, wid = threadIdx.x >> 5;
    if (lane == 0) {
        red[wid][0] = a_f;  red[wid][1] = a_w0; red[wid][2] = a_w0d;
        red[wid][3] = a_i;  red[wid][4] = a_p;  red[wid][5] = a_t;
        red[wid][6] = lmax;
    }
    __syncthreads();
    if (threadIdx.x == 0) {
        float s0=0, s1=0, s2=0, s3=0, s4=0, s5=0, m6=0;
        #pragma unroll
        for (int w = 0; w < 8; w++) {
            s0 += red[w][0]; s1 += red[w][1]; s2 += red[w][2];
            s3 += red[w][3]; s4 += red[w][4]; s5 += red[w][5];
            m6 = fmaxf(m6, red[w][6]);
        }
        atomicAdd(&g_acc[0],         (double)s0);
        atomicAdd(&g_acc[A_W0 + b],  (double)s1);
        atomicAdd(&g_acc[A_W0D + b], (double)s2);
        atomicAdd(&g_acc[A_I + b],   (double)s3);
        atomicAdd(&g_acc[A_P + b],   (double)s4);
        atomicAdd(&g_acc[A_T + b],   (double)s5);
        atomicMax(&g_maxdi[b], __float_as_int(m6));   // valid: m6 >= 0
    }
}

// ---------------------------------------------------------------------------
__global__ void finalize_kernel(const float* __restrict__ lv, float* __restrict__ out) {
    if (threadIdx.x == 0) {
        double N = (double)NTOT;
        double focal = g_acc[0] / N;
        double bsum = 0.0, dsum = 0.0, isum = 0.0;
        for (int b = 0; b < BB; b++) {
            double w0s  = g_acc[A_W0 + b];
            double w0ds = g_acc[A_W0D + b];
            double bnd_b;
            if (g_hasfg[b]) {
                float mx = __int_as_float(g_maxdi[b]);
                double scale = (mx > 0.0f) ? 1.0 / fmax((double)mx, 1e-12) : 1.0;
                bnd_b = w0s + scale * w0ds;   // sum w0*(1 + d/mx)
            } else {
                bnd_b = 2.0 * w0s;            // dist == 1 everywhere
            }
            bsum += bnd_b;
            double inter = g_acc[A_I + b];
            double tot = g_acc[A_P + b] + g_acc[A_T + b];
            dsum += (2.0 * inter + 1e-6) / (tot + 1e-6);
            isum += (inter + 1e-6) / (tot - inter + 1e-6);
        }
        double bnd  = bsum / N;
        double dice = 1.0 - dsum / (double)BB;
        double iou  = 1.0 - isum / (double)BB;
        float f = (float)focal, d = (float)dice, bb = (float)bnd, io = (float)iou;
        float total = expf(-lv[0]) * f + lv[0]
                    + expf(-lv[1]) * d + lv[1]
                    + expf(-lv[2]) * bb + lv[2]
                    + expf(-lv[3]) * io + lv[3];
        out[0] = total;
        out[1] = f;
        out[2] = d;
        out[3] = bb;
        out[4] = io;
    }
}

// ---------------------------------------------------------------------------
extern "C" void kernel_launch(void* const* d_in, const int* in_sizes, int n_in,
                              void* d_out, int out_size) {
    const float* pred = (const float*)d_in[0];
    const int*   tgt  = (const int*)d_in[1];
    const float* lv   = (const float*)d_in[2];
    float* out = (float*)d_out;

    zero_kernel<<<1, 128>>>();
    packbound_kernel<<<dim3(16, BB), 256>>>(tgt);
    dtloss_kernel<<<dim3(32, BB), 256>>>(pred);
    finalize_kernel<<<1, 32>>>(lv, out);
}

// round 8
// speedup vs baseline: 14.7714x; 1.4665x over previous
#include <cuda_runtime.h>
#include <math.h>

#define HH 512
#define WW 512
#define BB 16
#define NPIX (HH*WW)
#define NTOT (BB*NPIX)
#define WPR 16            // 32-bit words per row
#define WPS (HH*WPR)      // words per sample bitmap = 8192

#define F_A  0.955f
#define F_B  1.3693f
#define BA_C (1.3693f - 0.955f)
#define F_INF 1e6f

// acc layout: [0]=focal ; [1..16]=w0 ; [17..32]=w0*d ; [33..48]=inter ;
//             [49..64]=psum ; [65..80]=tsum
#define ACC_N 81
#define A_W0   1
#define A_W0D  17
#define A_I    33
#define A_P    49
#define A_T    65

#define DT_GRID_X 32
#define DT_BLOCKS (DT_GRID_X * BB)

// Scratch (device globals; zero-initialized at load, and self-reset at the
// end of every kernel_launch so replays are deterministic)
__device__ unsigned g_mbits[BB*WPS];     // mask bitmap
__device__ unsigned g_bbits[BB*WPS];     // boundary bitmap
__device__ int      g_maxdi[BB];         // per-sample max dist (float bits, >=0)
__device__ int      g_hasfg[BB];
__device__ int      g_hasb[BB];
__device__ int      g_anyzero[BB];
__device__ double   g_acc[ACC_N];
__device__ unsigned g_done;              // last-block counter (self-wrapping)

// ---------------------------------------------------------------------------
// Fused pack + boundary. Each block: sample b, 32 rows. Packs a 34-row halo
// slab of the target into shared bitmap, then computes the bitwise
// morphological boundary (pixel is boundary iff in-bounds 3x3 neighborhood,
// incl. self, contains both a 1 and a 0). Writes bitmaps + per-sample flags.
__global__ void __launch_bounds__(256) packbound_kernel(const int* __restrict__ tgt) {
    int b = blockIdx.y;
    int r0 = blockIdx.x * 32;
    __shared__ unsigned pm[34 * WPR];

    for (int w = threadIdx.x; w < 34 * WPR; w += 256) {
        int ri = w >> 4;              // 0..33  -> row r0-1+ri
        int wi = w & 15;
        int y = r0 - 1 + ri;
        unsigned word = 0;
        if ((unsigned)y < (unsigned)HH) {
            const int4* T = (const int4*)(tgt + b * NPIX + y * WW + wi * 32);
            #pragma unroll
            for (int q = 0; q < 8; q++) {
                int4 v = T[q];
                word |= (v.x != 0 ? 1u : 0u) << (q*4 + 0);
                word |= (v.y != 0 ? 1u : 0u) << (q*4 + 1);
                word |= (v.z != 0 ? 1u : 0u) << (q*4 + 2);
                word |= (v.w != 0 ? 1u : 0u) << (q*4 + 3);
            }
        }
        pm[w] = word;
    }
    __syncthreads();

    int fg = 0, bd = 0, az = 0;
    #pragma unroll 1
    for (int w = threadIdx.x; w < 32 * WPR; w += 256) {
        int lr = (w >> 4) + 1;        // local row 1..32
        int wi = w & 15;
        int y = r0 + (w >> 4);
        unsigned any1 = 0, any0 = 0;
        #pragma unroll
        for (int dr = -1; dr <= 1; dr++) {
            int y2 = y + dr;
            if ((unsigned)y2 >= (unsigned)HH) continue;
            int l2 = lr + dr;
            unsigned c  = pm[l2 * WPR + wi];
            unsigned lw = (wi > 0)  ? pm[l2 * WPR + wi - 1] : 0u;
            unsigned rw = (wi < 15) ? pm[l2 * WPR + wi + 1] : 0u;
            any1 |= c | (c << 1) | (lw >> 31) | (c >> 1) | (rw << 31);
            unsigned cn = ~c;
            unsigned ln = (wi > 0)  ? ~lw : 0u;   // outside image votes nothing
            unsigned rn = (wi < 15) ? ~rw : 0u;
            any0 |= cn | (cn << 1) | (ln >> 31) | (cn >> 1) | (rn << 31);
        }
        unsigned bw = any1 & any0;
        unsigned mw = pm[lr * WPR + wi];
        g_bbits[b * WPS + y * WPR + wi] = bw;
        g_mbits[b * WPS + y * WPR + wi] = mw;
        fg |= (mw != 0u);
        bd |= (bw != 0u);
        az |= (mw != 0xffffffffu);
    }
    fg = __syncthreads_or(fg);
    bd = __syncthreads_or(bd);
    az = __syncthreads_or(az);
    if (threadIdx.x == 0) {
        if (fg) atomicOr(&g_hasfg[b], 1);
        if (bd) atomicOr(&g_hasb[b], 1);
        if (az) atomicOr(&g_anyzero[b], 1);
    }
}

// ---------------------------------------------------------------------------
// Distance (in columns) from x to nearest set bit in a 512-bit row.
// Stops scanning words once no closer hit than min(found, cap) is possible.
__device__ __forceinline__ int nearest_bit(const unsigned* __restrict__ rw, int x, int cap) {
    int wi = x >> 5, bi = x & 31;
    unsigned w = rw[wi];
    int d = 1 << 29;
    unsigned lm = w << (31 - bi);               // bits <= bi
    if (lm) d = __clz(lm);
    unsigned rm = w >> bi;                      // bits >= bi
    if (rm) d = min(d, __ffs(rm) - 1);
    #pragma unroll 1
    for (int k = 1; k < WPR; k++) {
        int lwi = wi - k, rwi = wi + k;
        int dl = (lwi >= 0)  ? (bi + 32*k - 31) : (1 << 29);
        int dr = (rwi < WPR) ? (32*k - bi)      : (1 << 29);
        if (min(dl, dr) >= min(d, cap)) break;
        if (lwi >= 0) {
            unsigned lw = rw[lwi];
            if (lw) d = min(d, bi + 32*k - 31 + __clz(lw));
        }
        if (rwi < WPR) {
            unsigned rw2 = rw[rwi];
            if (rw2) d = min(d, 32*k - bi + __ffs(rw2) - 1);
        }
    }
    return d;
}

// ---------------------------------------------------------------------------
// Fused closed-form chamfer DT + loss + (last block) finalize + state reset.
__global__ void __launch_bounds__(256) dtloss_kernel(const float* __restrict__ pred,
                                                     const float* __restrict__ lv,
                                                     float* __restrict__ out) {
    int b = blockIdx.y;
    __shared__ unsigned sb[WPS];   // 32KB seed bitmap
    int hb = g_hasb[b];
    const unsigned* bs = g_bbits + b * WPS;
    const unsigned* ms = g_mbits + b * WPS;
    for (int i = threadIdx.x; i < WPS; i += 256)
        sb[i] = hb ? bs[i] : ~ms[i];
    __syncthreads();

    int hs = hb ? 1 : g_anyzero[b];
    int r0 = blockIdx.x * 16;
    float lmax = 0.0f;
    float a_f = 0.f, a_w0 = 0.f, a_w0d = 0.f, a_i = 0.f, a_p = 0.f, a_t = 0.f;

    #pragma unroll 1
    for (int rr = 0; rr < 16; rr++) {
        int y = r0 + rr;
        #pragma unroll
        for (int cc = 0; cc < 2; cc++) {
            int x = threadIdx.x + cc * 256;
            float best = F_INF;
            if (hs) {
                int nd = nearest_bit(sb + y * WPR, x, 600);
                if (nd < (1 << 28)) best = F_A * (float)nd;
                #pragma unroll 1
                for (int dy = 1; dy < HH; dy++) {
                    float ady = F_A * (float)dy;
                    if (ady >= best) break;
                    float capf = fmaxf((best - BA_C * (float)dy) * (1.0f / F_A),
                                       fminf((float)dy, (best - ady) * (1.0f / BA_C))) + 1.0f;
                    int cap = (int)fminf(capf, 600.0f);
                    int yu = y - dy;
                    if (yu >= 0) {
                        int nd2 = nearest_bit(sb + yu * WPR, x, cap);
                        if (nd2 < (1 << 28)) {
                            float f = (nd2 >= dy) ? (F_A * (float)nd2 + BA_C * (float)dy)
                                                  : (ady + BA_C * (float)nd2);
                            best = fminf(best, f);
                        }
                    }
                    int yd = y + dy;
                    if (yd < HH) {
                        int nd2 = nearest_bit(sb + yd * WPR, x, cap);
                        if (nd2 < (1 << 28)) {
                            float f = (nd2 >= dy) ? (F_A * (float)nd2 + BA_C * (float)dy)
                                                  : (ady + BA_C * (float)nd2);
                            best = fminf(best, f);
                        }
                    }
                }
            }
            lmax = fmaxf(lmax, best);

            // ---- loss terms for this pixel ----
            int gi = b * NPIX + y * WW + x;
            float xv = pred[gi];
            float t = (float)((ms[y * WPR + (x >> 5)] >> (x & 31)) & 1u);
            float e = __expf(-fabsf(xv));
            float l1p = __logf(1.0f + e);
            float s = __fdividef(1.0f, 1.0f + e);
            float p = (xv >= 0.0f) ? s : 1.0f - s;            // sigmoid
            float ls_x  = fminf(xv, 0.0f)  - l1p;             // log sigmoid(x)
            float ls_nx = fminf(-xv, 0.0f) - l1p;             // log sigmoid(-x)
            float bce = -(t * ls_x + (1.0f - t) * ls_nx);
            float pt = t * p + (1.0f - t) * (1.0f - p);
            float at = (t == 1.0f) ? 0.25f : 0.75f;
            float om = 1.0f - pt;
            a_f += at * om * om * bce;
            float w0 = t * (1.0f - p) + (1.0f - t) * p;
            a_w0  += w0;
            a_w0d += w0 * best;
            a_i += p * t;
            a_p += p;
            a_t += t;
        }
    }

    // block reduce 6 sums + max
    #pragma unroll
    for (int o = 16; o > 0; o >>= 1) {
        a_f   += __shfl_down_sync(0xffffffffu, a_f,   o);
        a_w0  += __shfl_down_sync(0xffffffffu, a_w0,  o);
        a_w0d += __shfl_down_sync(0xffffffffu, a_w0d, o);
        a_i   += __shfl_down_sync(0xffffffffu, a_i,   o);
        a_p   += __shfl_down_sync(0xffffffffu, a_p,   o);
        a_t   += __shfl_down_sync(0xffffffffu, a_t,   o);
        lmax   = fmaxf(lmax, __shfl_down_sync(0xffffffffu, lmax, o));
    }
    __shared__ float red[8][7];
    int lane = threadIdx.x & 31, wid = threadIdx.x >> 5;
    if (lane == 0) {
        red[wid][0] = a_f;  red[wid][1] = a_w0; red[wid][2] = a_w0d;
        red[wid][3] = a_i;  red[wid][4] = a_p;  red[wid][5] = a_t;
        red[wid][6] = lmax;
    }
    __syncthreads();
    if (threadIdx.x == 0) {
        float s0=0, s1=0, s2=0, s3=0, s4=0, s5=0, m6=0;
        #pragma unroll
        for (int w = 0; w < 8; w++) {
            s0 += red[w][0]; s1 += red[w][1]; s2 += red[w][2];
            s3 += red[w][3]; s4 += red[w][4]; s5 += red[w][5];
            m6 = fmaxf(m6, red[w][6]);
        }
        atomicAdd(&g_acc[0],         (double)s0);
        atomicAdd(&g_acc[A_W0 + b],  (double)s1);
        atomicAdd(&g_acc[A_W0D + b], (double)s2);
        atomicAdd(&g_acc[A_I + b],   (double)s3);
        atomicAdd(&g_acc[A_P + b],   (double)s4);
        atomicAdd(&g_acc[A_T + b],   (double)s5);
        atomicMax(&g_maxdi[b], __float_as_int(m6));   // valid: m6 >= 0
    }

    // ---- last-block finalize (threadfence reduction idiom) ----
    __shared__ int isLast;
    __threadfence();
    if (threadIdx.x == 0) {
        unsigned n = atomicInc(&g_done, DT_BLOCKS - 1);   // wraps to 0 on last
        isLast = (n == DT_BLOCKS - 1);
    }
    __syncthreads();
    if (!isLast) return;

    // One warp: lane b (0..15) handles sample b; parallel loads hide latency.
    if (wid == 0) {
        double bnd_b = 0.0, dice_b = 0.0, iou_b = 0.0;
        if (lane < BB) {
            int bb2 = lane;
            double w0s  = g_acc[A_W0 + bb2];
            double w0ds = g_acc[A_W0D + bb2];
            if (g_hasfg[bb2]) {
                float mx = __int_as_float(g_maxdi[bb2]);
                double scale = (mx > 0.0f) ? 1.0 / fmax((double)mx, 1e-12) : 1.0;
                bnd_b = w0s + scale * w0ds;   // sum w0*(1 + d/mx)
            } else {
                bnd_b = 2.0 * w0s;            // dist == 1 everywhere
            }
            double inter = g_acc[A_I + bb2];
            double tot = g_acc[A_P + bb2] + g_acc[A_T + bb2];
            dice_b = (2.0 * inter + 1e-6) / (tot + 1e-6);
            iou_b  = (inter + 1e-6) / (tot - inter + 1e-6);
        }
        #pragma unroll
        for (int o = 8; o > 0; o >>= 1) {
            bnd_b  += __shfl_down_sync(0xffffffffu, bnd_b,  o);
            dice_b += __shfl_down_sync(0xffffffffu, dice_b, o);
            iou_b  += __shfl_down_sync(0xffffffffu, iou_b,  o);
        }
        if (lane == 0) {
            double N = (double)NTOT;
            double focal = g_acc[0] / N;
            double bnd   = bnd_b / N;
            double dice  = 1.0 - dice_b / (double)BB;
            double iou   = 1.0 - iou_b / (double)BB;
            float f = (float)focal, d = (float)dice, bo = (float)bnd, io = (float)iou;
            float total = expf(-lv[0]) * f + lv[0]
                        + expf(-lv[1]) * d + lv[1]
                        + expf(-lv[2]) * bo + lv[2]
                        + expf(-lv[3]) * io + lv[3];
            out[0] = total;
            out[1] = f;
            out[2] = d;
            out[3] = bo;
            out[4] = io;
        }
    }
    __syncthreads();
    // reset accumulator state for the next (deterministic) replay
    if (threadIdx.x < ACC_N) g_acc[threadIdx.x] = 0.0;
    if (threadIdx.x >= 128 && threadIdx.x < 128 + BB) {
        int t = threadIdx.x - 128;
        g_hasfg[t] = 0; g_hasb[t] = 0; g_anyzero[t] = 0; g_maxdi[t] = 0;
    }
}

// ---------------------------------------------------------------------------
extern "C" void kernel_launch(void* const* d_in, const int* in_sizes, int n_in,
                              void* d_out, int out_size) {
    const float* pred = (const float*)d_in[0];
    const int*   tgt  = (const int*)d_in[1];
    const float* lv   = (const float*)d_in[2];
    float* out = (float*)d_out;

    packbound_kernel<<<dim3(16, BB), 256>>>(tgt);
    dtloss_kernel<<<dim3(DT_GRID_X, BB), 256>>>(pred, lv, out);
}

// round 9
// speedup vs baseline: 16.9750x; 1.1492x over previous
#include <cuda_runtime.h>
#include <math.h>

#define HH 512
#define WW 512
#define BB 16
#define NPIX (HH*WW)
#define NTOT (BB*NPIX)
#define WPR 16            // 32-bit words per row
#define WPS (HH*WPR)      // words per sample bitmap = 8192

#define F_A  0.955f
#define F_B  1.3693f
#define BA_C (1.3693f - 0.955f)
#define F_INF 1e6f

// acc layout: 6 arrays of BB doubles
#define A_F    0
#define A_W0   16
#define A_W0D  32
#define A_I    48
#define A_P    64
#define A_T    80
#define ACC_N  96

#define DT_GRID_X 64              // 8 rows per block
#define DT_BLOCKS (DT_GRID_X * BB)

// Scratch (device globals; zero-initialized at load, self-reset each launch)
__device__ unsigned g_mbits[BB*WPS];     // mask bitmap
__device__ unsigned g_bbits[BB*WPS];     // boundary bitmap
__device__ int      g_maxdi[BB];         // per-sample max dist (float bits, >=0)
__device__ int      g_hasfg[BB];
__device__ int      g_hasb[BB];
__device__ int      g_anyzero[BB];
__device__ double   g_acc[ACC_N];
__device__ unsigned g_done;              // last-block counter (self-wrapping)

// ---------------------------------------------------------------------------
// Fused pack + boundary. Each block: sample b, 32 rows. Packs a 34-row halo
// slab into a shared bitmap, then the bitwise morphological boundary (pixel
// is boundary iff in-bounds 3x3 neighborhood, incl. self, has both 1 and 0).
__global__ void __launch_bounds__(256) packbound_kernel(const int* __restrict__ tgt) {
    int b = blockIdx.y;
    int r0 = blockIdx.x * 32;
    __shared__ unsigned pm[34 * WPR];

    for (int w = threadIdx.x; w < 34 * WPR; w += 256) {
        int ri = w >> 4;              // 0..33  -> row r0-1+ri
        int wi = w & 15;
        int y = r0 - 1 + ri;
        unsigned word = 0;
        if ((unsigned)y < (unsigned)HH) {
            const int4* T = (const int4*)(tgt + b * NPIX + y * WW + wi * 32);
            #pragma unroll
            for (int q = 0; q < 8; q++) {
                int4 v = T[q];
                word |= (v.x != 0 ? 1u : 0u) << (q*4 + 0);
                word |= (v.y != 0 ? 1u : 0u) << (q*4 + 1);
                word |= (v.z != 0 ? 1u : 0u) << (q*4 + 2);
                word |= (v.w != 0 ? 1u : 0u) << (q*4 + 3);
            }
        }
        pm[w] = word;
    }
    __syncthreads();

    int fg = 0, bd = 0, az = 0;
    #pragma unroll 1
    for (int w = threadIdx.x; w < 32 * WPR; w += 256) {
        int lr = (w >> 4) + 1;        // local row 1..32
        int wi = w & 15;
        int y = r0 + (w >> 4);
        unsigned any1 = 0, any0 = 0;
        #pragma unroll
        for (int dr = -1; dr <= 1; dr++) {
            int y2 = y + dr;
            if ((unsigned)y2 >= (unsigned)HH) continue;
            int l2 = lr + dr;
            unsigned c  = pm[l2 * WPR + wi];
            unsigned lw = (wi > 0)  ? pm[l2 * WPR + wi - 1] : 0u;
            unsigned rw = (wi < 15) ? pm[l2 * WPR + wi + 1] : 0u;
            any1 |= c | (c << 1) | (lw >> 31) | (c >> 1) | (rw << 31);
            unsigned cn = ~c;
            unsigned ln = (wi > 0)  ? ~lw : 0u;   // outside image votes nothing
            unsigned rn = (wi < 15) ? ~rw : 0u;
            any0 |= cn | (cn << 1) | (ln >> 31) | (cn >> 1) | (rn << 31);
        }
        unsigned bw = any1 & any0;
        unsigned mw = pm[lr * WPR + wi];
        g_bbits[b * WPS + y * WPR + wi] = bw;
        g_mbits[b * WPS + y * WPR + wi] = mw;
        fg |= (mw != 0u);
        bd |= (bw != 0u);
        az |= (mw != 0xffffffffu);
    }
    fg = __syncthreads_or(fg);
    bd = __syncthreads_or(bd);
    az = __syncthreads_or(az);
    if (threadIdx.x == 0) {
        if (fg) atomicOr(&g_hasfg[b], 1);
        if (bd) atomicOr(&g_hasb[b], 1);
        if (az) atomicOr(&g_anyzero[b], 1);
    }
}

// ---------------------------------------------------------------------------
// Distance (in columns) from x to nearest set bit in a 512-bit row.
// Stops scanning words once no closer hit than min(found, cap) is possible.
__device__ __forceinline__ int nearest_bit(const unsigned* __restrict__ rw, int x, int cap) {
    int wi = x >> 5, bi = x & 31;
    unsigned w = rw[wi];
    int d = 1 << 29;
    unsigned lm = w << (31 - bi);               // bits <= bi
    if (lm) d = __clz(lm);
    unsigned rm = w >> bi;                      // bits >= bi
    if (rm) d = min(d, __ffs(rm) - 1);
    #pragma unroll 1
    for (int k = 1; k < WPR; k++) {
        int lwi = wi - k, rwi = wi + k;
        int dl = (lwi >= 0)  ? (bi + 32*k - 31) : (1 << 29);
        int dr = (rwi < WPR) ? (32*k - bi)      : (1 << 29);
        if (min(dl, dr) >= min(d, cap)) break;
        if (lwi >= 0) {
            unsigned lw = rw[lwi];
            if (lw) d = min(d, bi + 32*k - 31 + __clz(lw));
        }
        if (rwi < WPR) {
            unsigned rw2 = rw[rwi];
            if (rw2) d = min(d, 32*k - bi + __ffs(rw2) - 1);
        }
    }
    return d;
}

// ---------------------------------------------------------------------------
// Fused closed-form chamfer DT + loss + (last block) finalize + state reset.
// Each block: 8 rows of one sample.
__global__ void __launch_bounds__(256) dtloss_kernel(const float* __restrict__ pred,
                                                     const float* __restrict__ lv,
                                                     float* __restrict__ out) {
    int b = blockIdx.y;
    __shared__ unsigned sb[WPS];   // 32KB seed bitmap
    int hb = g_hasb[b];
    const unsigned* ms = g_mbits + b * WPS;
    {
        uint4* d4 = (uint4*)sb;
        if (hb) {
            const uint4* s4 = (const uint4*)(g_bbits + b * WPS);
            #pragma unroll
            for (int i = threadIdx.x; i < WPS/4; i += 256) d4[i] = s4[i];
        } else {
            const uint4* s4 = (const uint4*)ms;
            #pragma unroll
            for (int i = threadIdx.x; i < WPS/4; i += 256) {
                uint4 v = s4[i];
                v.x = ~v.x; v.y = ~v.y; v.z = ~v.z; v.w = ~v.w;
                d4[i] = v;
            }
        }
    }
    __syncthreads();

    int hs = hb ? 1 : g_anyzero[b];
    int r0 = blockIdx.x * 8;
    float lmax = 0.0f;
    float a_f = 0.f, a_w0 = 0.f, a_w0d = 0.f, a_i = 0.f, a_p = 0.f, a_t = 0.f;

    #pragma unroll 1
    for (int rr = 0; rr < 8; rr++) {
        int y = r0 + rr;
        #pragma unroll
        for (int cc = 0; cc < 2; cc++) {
            int x = threadIdx.x + cc * 256;
            float best = F_INF;
            if (hs) {
                int nd = nearest_bit(sb + y * WPR, x, 600);
                if (nd < (1 << 28)) best = F_A * (float)nd;
                #pragma unroll 1
                for (int dy = 1; dy < HH; dy++) {
                    float ady = F_A * (float)dy;
                    if (ady >= best) break;
                    float capf = fmaxf((best - BA_C * (float)dy) * (1.0f / F_A),
                                       fminf((float)dy, (best - ady) * (1.0f / BA_C))) + 1.0f;
                    int cap = (int)fminf(capf, 600.0f);
                    int yu = y - dy;
                    if (yu >= 0) {
                        int nd2 = nearest_bit(sb + yu * WPR, x, cap);
                        if (nd2 < (1 << 28)) {
                            float f = (nd2 >= dy) ? (F_A * (float)nd2 + BA_C * (float)dy)
                                                  : (ady + BA_C * (float)nd2);
                            best = fminf(best, f);
                        }
                    }
                    int yd = y + dy;
                    if (yd < HH) {
                        int nd2 = nearest_bit(sb + yd * WPR, x, cap);
                        if (nd2 < (1 << 28)) {
                            float f = (nd2 >= dy) ? (F_A * (float)nd2 + BA_C * (float)dy)
                                                  : (ady + BA_C * (float)nd2);
                            best = fminf(best, f);
                        }
                    }
                }
            }
            lmax = fmaxf(lmax, best);

            // ---- loss terms (t in {0,1}: selects replace multiplies; values
            //      bit-identical to the t-weighted forms) ----
            int gi = b * NPIX + y * WW + x;
            float xv = pred[gi];
            int tb = (ms[y * WPR + (x >> 5)] >> (x & 31)) & 1u;
            float e = __expf(-fabsf(xv));
            float l1p = __logf(1.0f + e);
            float s = __fdividef(1.0f, 1.0f + e);
            float p = (xv >= 0.0f) ? s : 1.0f - s;            // sigmoid
            float pt = tb ? p : 1.0f - p;
            float om = 1.0f - pt;                              // == w0
            float bce = l1p - (tb ? fminf(xv, 0.0f) : fminf(-xv, 0.0f));
            float at = tb ? 0.25f : 0.75f;
            a_f  += at * om * om * bce;
            a_w0 += om;
            a_w0d += om * best;
            if (tb) { a_i += p; a_t += 1.0f; }
            a_p += p;
        }
    }

    // block reduce 6 sums + max
    #pragma unroll
    for (int o = 16; o > 0; o >>= 1) {
        a_f   += __shfl_down_sync(0xffffffffu, a_f,   o);
        a_w0  += __shfl_down_sync(0xffffffffu, a_w0,  o);
        a_w0d += __shfl_down_sync(0xffffffffu, a_w0d, o);
        a_i   += __shfl_down_sync(0xffffffffu, a_i,   o);
        a_p   += __shfl_down_sync(0xffffffffu, a_p,   o);
        a_t   += __shfl_down_sync(0xffffffffu, a_t,   o);
        lmax   = fmaxf(lmax, __shfl_down_sync(0xffffffffu, lmax, o));
    }
    __shared__ float red[8][7];
    int lane = threadIdx.x & 31, wid = threadIdx.x >> 5;
    if (lane == 0) {
        red[wid][0] = a_f;  red[wid][1] = a_w0; red[wid][2] = a_w0d;
        red[wid][3] = a_i;  red[wid][4] = a_p;  red[wid][5] = a_t;
        red[wid][6] = lmax;
    }
    __syncthreads();
    if (threadIdx.x == 0) {
        float s0=0, s1=0, s2=0, s3=0, s4=0, s5=0, m6=0;
        #pragma unroll
        for (int w = 0; w < 8; w++) {
            s0 += red[w][0]; s1 += red[w][1]; s2 += red[w][2];
            s3 += red[w][3]; s4 += red[w][4]; s5 += red[w][5];
            m6 = fmaxf(m6, red[w][6]);
        }
        atomicAdd(&g_acc[A_F + b],   (double)s0);
        atomicAdd(&g_acc[A_W0 + b],  (double)s1);
        atomicAdd(&g_acc[A_W0D + b], (double)s2);
        atomicAdd(&g_acc[A_I + b],   (double)s3);
        atomicAdd(&g_acc[A_P + b],   (double)s4);
        atomicAdd(&g_acc[A_T + b],   (double)s5);
        atomicMax(&g_maxdi[b], __float_as_int(m6));   // valid: m6 >= 0
    }

    // ---- last-block finalize (threadfence reduction idiom) ----
    __shared__ int isLast;
    __threadfence();
    if (threadIdx.x == 0) {
        unsigned n = atomicInc(&g_done, DT_BLOCKS - 1);   // wraps to 0 on last
        isLast = (n == DT_BLOCKS - 1);
    }
    __syncthreads();
    if (!isLast) return;

    // One warp: lane b (0..15) handles sample b; parallel loads hide latency.
    if (wid == 0) {
        double f_b = 0.0, bnd_b = 0.0, dice_b = 0.0, iou_b = 0.0;
        if (lane < BB) {
            int bb2 = lane;
            f_b = g_acc[A_F + bb2];
            double w0s  = g_acc[A_W0 + bb2];
            double w0ds = g_acc[A_W0D + bb2];
            if (g_hasfg[bb2]) {
                float mx = __int_as_float(g_maxdi[bb2]);
                double scale = (mx > 0.0f) ? 1.0 / fmax((double)mx, 1e-12) : 1.0;
                bnd_b = w0s + scale * w0ds;   // sum w0*(1 + d/mx)
            } else {
                bnd_b = 2.0 * w0s;            // dist == 1 everywhere
            }
            double inter = g_acc[A_I + bb2];
            double tot = g_acc[A_P + bb2] + g_acc[A_T + bb2];
            dice_b = (2.0 * inter + 1e-6) / (tot + 1e-6);
            iou_b  = (inter + 1e-6) / (tot - inter + 1e-6);
        }
        #pragma unroll
        for (int o = 8; o > 0; o >>= 1) {
            f_b    += __shfl_down_sync(0xffffffffu, f_b,    o);
            bnd_b  += __shfl_down_sync(0xffffffffu, bnd_b,  o);
            dice_b += __shfl_down_sync(0xffffffffu, dice_b, o);
            iou_b  += __shfl_down_sync(0xffffffffu, iou_b,  o);
        }
        if (lane == 0) {
            double N = (double)NTOT;
            double focal = f_b / N;
            double bnd   = bnd_b / N;
            double dice  = 1.0 - dice_b / (double)BB;
            double iou   = 1.0 - iou_b / (double)BB;
            float f = (float)focal, d = (float)dice, bo = (float)bnd, io = (float)iou;
            float total = expf(-lv[0]) * f + lv[0]
                        + expf(-lv[1]) * d + lv[1]
                        + expf(-lv[2]) * bo + lv[2]
                        + expf(-lv[3]) * io + lv[3];
            out[0] = total;
            out[1] = f;
            out[2] = d;
            out[3] = bo;
            out[4] = io;
        }
    }
    __syncthreads();
    // reset accumulator state for the next (deterministic) replay
    if (threadIdx.x < ACC_N) g_acc[threadIdx.x] = 0.0;
    if (threadIdx.x >= 128 && threadIdx.x < 128 + BB) {
        int t = threadIdx.x - 128;
        g_hasfg[t] = 0; g_hasb[t] = 0; g_anyzero[t] = 0; g_maxdi[t] = 0;
    }
}

// ---------------------------------------------------------------------------
extern "C" void kernel_launch(void* const* d_in, const int* in_sizes, int n_in,
                              void* d_out, int out_size) {
    const float* pred = (const float*)d_in[0];
    const int*   tgt  = (const int*)d_in[1];
    const float* lv   = (const float*)d_in[2];
    float* out = (float*)d_out;

    packbound_kernel<<<dim3(16, BB), 256>>>(tgt);
    dtloss_kernel<<<dim3(DT_GRID_X, BB), 256>>>(pred, lv, out);
}

// round 11
// speedup vs baseline: 18.3146x; 1.0789x over previous
#include <cuda_runtime.h>
#include <math.h>

#define HH 512
#define WW 512
#define BB 16
#define NPIX (HH*WW)
#define NTOT (BB*NPIX)
#define WPR 16            // 32-bit words per row
#define WPS (HH*WPR)      // words per sample bitmap = 8192

#define F_A  0.955f
#define F_B  1.3693f
#define BA_C (1.3693f - 0.955f)
#define F_INF 1e6f

// acc layout: 6 arrays of BB doubles
#define A_F    0
#define A_W0   16
#define A_W0D  32
#define A_I    48
#define A_P    64
#define A_T    80
#define ACC_N  96

#define DT_GRID_X 64              // 8 rows per block
#define DT_BLOCKS (DT_GRID_X * BB)

// Scratch (device globals; zero-initialized at load, self-reset each launch)
__device__ unsigned g_mbits[BB*WPS];     // mask bitmap
__device__ unsigned g_bbits[BB*WPS];     // boundary bitmap
__device__ int      g_maxdi[BB];         // per-sample max dist (float bits, >=0)
__device__ int      g_hasfg[BB];
__device__ int      g_hasb[BB];
__device__ int      g_anyzero[BB];
__device__ double   g_acc[ACC_N];
__device__ unsigned g_done;              // last-block counter (self-wrapping)

// ---------------------------------------------------------------------------
// Fused pack + boundary. Each block: sample b, 32 rows. Packs a 34-row halo
// slab into a shared bitmap, then the bitwise morphological boundary (pixel
// is boundary iff in-bounds 3x3 neighborhood, incl. self, has both 1 and 0).
__global__ void __launch_bounds__(256) packbound_kernel(const int* __restrict__ tgt) {
    int b = blockIdx.y;
    int r0 = blockIdx.x * 32;
    __shared__ unsigned pm[34 * WPR];

    for (int w = threadIdx.x; w < 34 * WPR; w += 256) {
        int ri = w >> 4;              // 0..33  -> row r0-1+ri
        int wi = w & 15;
        int y = r0 - 1 + ri;
        unsigned word = 0;
        if ((unsigned)y < (unsigned)HH) {
            const int4* T = (const int4*)(tgt + b * NPIX + y * WW + wi * 32);
            #pragma unroll
            for (int q = 0; q < 8; q++) {
                int4 v = T[q];
                word |= (v.x != 0 ? 1u : 0u) << (q*4 + 0);
                word |= (v.y != 0 ? 1u : 0u) << (q*4 + 1);
                word |= (v.z != 0 ? 1u : 0u) << (q*4 + 2);
                word |= (v.w != 0 ? 1u : 0u) << (q*4 + 3);
            }
        }
        pm[w] = word;
    }
    __syncthreads();

    int fg = 0, bd = 0, az = 0;
    #pragma unroll 1
    for (int w = threadIdx.x; w < 32 * WPR; w += 256) {
        int lr = (w >> 4) + 1;        // local row 1..32
        int wi = w & 15;
        int y = r0 + (w >> 4);
        unsigned any1 = 0, any0 = 0;
        #pragma unroll
        for (int dr = -1; dr <= 1; dr++) {
            int y2 = y + dr;
            if ((unsigned)y2 >= (unsigned)HH) continue;
            int l2 = lr + dr;
            unsigned c  = pm[l2 * WPR + wi];
            unsigned lw = (wi > 0)  ? pm[l2 * WPR + wi - 1] : 0u;
            unsigned rw = (wi < 15) ? pm[l2 * WPR + wi + 1] : 0u;
            any1 |= c | (c << 1) | (lw >> 31) | (c >> 1) | (rw << 31);
            unsigned cn = ~c;
            unsigned ln = (wi > 0)  ? ~lw : 0u;   // outside image votes nothing
            unsigned rn = (wi < 15) ? ~rw : 0u;
            any0 |= cn | (cn << 1) | (ln >> 31) | (cn >> 1) | (rn << 31);
        }
        unsigned bw = any1 & any0;
        unsigned mw = pm[lr * WPR + wi];
        g_bbits[b * WPS + y * WPR + wi] = bw;
        g_mbits[b * WPS + y * WPR + wi] = mw;
        fg |= (mw != 0u);
        bd |= (bw != 0u);
        az |= (mw != 0xffffffffu);
    }
    fg = __syncthreads_or(fg);
    bd = __syncthreads_or(bd);
    az = __syncthreads_or(az);
    if (threadIdx.x == 0) {
        if (fg) atomicOr(&g_hasfg[b], 1);
        if (bd) atomicOr(&g_hasb[b], 1);
        if (az) atomicOr(&g_anyzero[b], 1);
    }
}

// ---------------------------------------------------------------------------
// Distance (in columns) from x to nearest set bit in a 512-bit row.
__device__ __forceinline__ int nearest_bit(const unsigned* __restrict__ rw, int x, int cap) {
    int wi = x >> 5, bi = x & 31;
    unsigned w = rw[wi];
    int d = 1 << 29;
    unsigned lm = w << (31 - bi);               // bits <= bi
    if (lm) d = __clz(lm);
    unsigned rm = w >> bi;                      // bits >= bi
    if (rm) d = min(d, __ffs(rm) - 1);
    #pragma unroll 1
    for (int k = 1; k < WPR; k++) {
        int lwi = wi - k, rwi = wi + k;
        int dl = (lwi >= 0)  ? (bi + 32*k - 31) : (1 << 29);
        int dr = (rwi < WPR) ? (32*k - bi)      : (1 << 29);
        if (min(dl, dr) >= min(d, cap)) break;
        if (lwi >= 0) {
            unsigned lw = rw[lwi];
            if (lw) d = min(d, bi + 32*k - 31 + __clz(lw));
        }
        if (rwi < WPR) {
            unsigned rw2 = rw[rwi];
            if (rw2) d = min(d, 32*k - bi + __ffs(rw2) - 1);
        }
    }
    return d;
}

// Cold path: full closed-form search when the pixel itself is not a seed.
__device__ __noinline__ float dt_search(const unsigned* __restrict__ sb, int y, int x) {
    float best = F_INF;
    int nd = nearest_bit(sb + y * WPR, x, 600);
    if (nd < (1 << 28)) best = F_A * (float)nd;
    #pragma unroll 1
    for (int dy = 1; dy < HH; dy++) {
        float ady = F_A * (float)dy;
        if (ady >= best) break;
        float capf = fmaxf((best - BA_C * (float)dy) * (1.0f / F_A),
                           fminf((float)dy, (best - ady) * (1.0f / BA_C))) + 1.0f;
        int cap = (int)fminf(capf, 600.0f);
        int yu = y - dy;
        if (yu >= 0) {
            int nd2 = nearest_bit(sb + yu * WPR, x, cap);
            if (nd2 < (1 << 28)) {
                float f = (nd2 >= dy) ? (F_A * (float)nd2 + BA_C * (float)dy)
                                      : (ady + BA_C * (float)nd2);
                best = fminf(best, f);
            }
        }
        int yd = y + dy;
        if (yd < HH) {
            int nd2 = nearest_bit(sb + yd * WPR, x, cap);
            if (nd2 < (1 << 28)) {
                float f = (nd2 >= dy) ? (F_A * (float)nd2 + BA_C * (float)dy)
                                      : (ady + BA_C * (float)nd2);
                best = fminf(best, f);
            }
        }
    }
    return best;
}

// ---------------------------------------------------------------------------
// Fused closed-form chamfer DT + loss + (last block) finalize + state reset.
// Each block: 8 rows of one sample; each thread: 4 consecutive pixels x 4 its.
// NOTE: pred is loaded with SCALAR loads only — d_in pointers are not
// guaranteed 16B-aligned (misaligned-address fault with float4 in R9).
__global__ void __launch_bounds__(256) dtloss_kernel(const float* __restrict__ pred,
                                                     const float* __restrict__ lv,
                                                     float* __restrict__ out) {
    int b = blockIdx.y;
    __shared__ unsigned sb[WPS];   // 32KB seed bitmap
    int hb = g_hasb[b];
    const unsigned* ms = g_mbits + b * WPS;
    {
        // word-wise copy (device globals are 4B elements; avoid vector casts)
        if (hb) {
            const unsigned* s = g_bbits + b * WPS;
            #pragma unroll
            for (int i = threadIdx.x; i < WPS; i += 256) sb[i] = s[i];
        } else {
            #pragma unroll
            for (int i = threadIdx.x; i < WPS; i += 256) sb[i] = ~ms[i];
        }
    }
    __syncthreads();

    int hs = hb ? 1 : g_anyzero[b];
    int r0 = blockIdx.x * 8;
    float lmax = 0.0f;
    float a_f = 0.f, a_w0 = 0.f, a_w0d = 0.f, a_i = 0.f, a_p = 0.f, a_t = 0.f;

    const int x0 = (threadIdx.x & 127) * 4;
    const int ysub = threadIdx.x >> 7;       // 0 or 1

    #pragma unroll 1
    for (int it = 0; it < 4; it++) {
        int y = r0 + it * 2 + ysub;
        int wy = y * WPR + (x0 >> 5);
        unsigned snib = (sb[wy] >> (x0 & 31)) & 0xFu;
        unsigned mnib = (ms[wy] >> (x0 & 31)) & 0xFu;
        const float* pp = pred + b * NPIX + y * WW + x0;
        float xs0 = pp[0], xs1 = pp[1], xs2 = pp[2], xs3 = pp[3];

        #pragma unroll
        for (int k = 0; k < 4; k++) {
            float best;
            if ((snib >> k) & 1u)      best = 0.0f;          // pixel is a seed
            else if (hs)               best = dt_search(sb, y, x0 + k);
            else                       best = F_INF;
            lmax = fmaxf(lmax, best);

            int tb = (mnib >> k) & 1u;
            float xv = (k == 0) ? xs0 : (k == 1) ? xs1 : (k == 2) ? xs2 : xs3;
            // u = tb ? -x : x ; om = sigmoid(u) ; bce = softplus(u)
            float u = tb ? -xv : xv;
            float e = __expf(-fabsf(xv));
            float r = __fdividef(1.0f, 1.0f + e);
            float om = (u >= 0.0f) ? r : 1.0f - r;
            float bce = fmaxf(u, 0.0f) + __logf(1.0f + e);
            float p = tb ? 1.0f - om : om;                    // sigmoid(x)
            float at = tb ? 0.25f : 0.75f;
            a_f   += at * om * om * bce;
            a_w0  += om;
            a_w0d += om * best;
            if (tb) { a_i += p; a_t += 1.0f; }
            a_p += p;
        }
    }

    // block reduce 6 sums + max
    #pragma unroll
    for (int o = 16; o > 0; o >>= 1) {
        a_f   += __shfl_down_sync(0xffffffffu, a_f,   o);
        a_w0  += __shfl_down_sync(0xffffffffu, a_w0,  o);
        a_w0d += __shfl_down_sync(0xffffffffu, a_w0d, o);
        a_i   += __shfl_down_sync(0xffffffffu, a_i,   o);
        a_p   += __shfl_down_sync(0xffffffffu, a_p,   o);
        a_t   += __shfl_down_sync(0xffffffffu, a_t,   o);
        lmax   = fmaxf(lmax, __shfl_down_sync(0xffffffffu, lmax, o));
    }
    __shared__ float red[8][7];
    int lane = threadIdx.x & 31, wid = threadIdx.x >> 5;
    if (lane == 0) {
        red[wid][0] = a_f;  red[wid][1] = a_w0; red[wid][2] = a_w0d;
        red[wid][3] = a_i;  red[wid][4] = a_p;  red[wid][5] = a_t;
        red[wid][6] = lmax;
    }
    __syncthreads();
    if (threadIdx.x == 0) {
        float s0=0, s1=0, s2=0, s3=0, s4=0, s5=0, m6=0;
        #pragma unroll
        for (int w = 0; w < 8; w++) {
            s0 += red[w][0]; s1 += red[w][1]; s2 += red[w][2];
            s3 += red[w][3]; s4 += red[w][4]; s5 += red[w][5];
            m6 = fmaxf(m6, red[w][6]);
        }
        atomicAdd(&g_acc[A_F + b],   (double)s0);
        atomicAdd(&g_acc[A_W0 + b],  (double)s1);
        atomicAdd(&g_acc[A_W0D + b], (double)s2);
        atomicAdd(&g_acc[A_I + b],   (double)s3);
        atomicAdd(&g_acc[A_P + b],   (double)s4);
        atomicAdd(&g_acc[A_T + b],   (double)s5);
        atomicMax(&g_maxdi[b], __float_as_int(m6));   // valid: m6 >= 0
    }

    // ---- last-block finalize (threadfence reduction idiom) ----
    __shared__ int isLast;
    __threadfence();
    if (threadIdx.x == 0) {
        unsigned n = atomicInc(&g_done, DT_BLOCKS - 1);   // wraps to 0 on last
        isLast = (n == DT_BLOCKS - 1);
    }
    __syncthreads();
    if (!isLast) return;

    // One warp: lane b (0..15) handles sample b; parallel loads hide latency.
    if (wid == 0) {
        double f_b = 0.0, bnd_b = 0.0, dice_b = 0.0, iou_b = 0.0;
        if (lane < BB) {
            int bb2 = lane;
            f_b = g_acc[A_F + bb2];
            double w0s  = g_acc[A_W0 + bb2];
            double w0ds = g_acc[A_W0D + bb2];
            if (g_hasfg[bb2]) {
                float mx = __int_as_float(g_maxdi[bb2]);
                double scale = (mx > 0.0f) ? 1.0 / fmax((double)mx, 1e-12) : 1.0;
                bnd_b = w0s + scale * w0ds;   // sum w0*(1 + d/mx)
            } else {
                bnd_b = 2.0 * w0s;            // dist == 1 everywhere
            }
            double inter = g_acc[A_I + bb2];
            double tot = g_acc[A_P + bb2] + g_acc[A_T + bb2];
            dice_b = (2.0 * inter + 1e-6) / (tot + 1e-6);
            iou_b  = (inter + 1e-6) / (tot - inter + 1e-6);
        }
        #pragma unroll
        for (int o = 8; o > 0; o >>= 1) {
            f_b    += __shfl_down_sync(0xffffffffu, f_b,    o);
            bnd_b  += __shfl_down_sync(0xffffffffu, bnd_b,  o);
            dice_b += __shfl_down_sync(0xffffffffu, dice_b, o);
            iou_b  += __shfl_down_sync(0xffffffffu, iou_b,  o);
        }
        if (lane == 0) {
            double N = (double)NTOT;
            double focal = f_b / N;
            double bnd   = bnd_b / N;
            double dice  = 1.0 - dice_b / (double)BB;
            double iou   = 1.0 - iou_b / (double)BB;
            float f = (float)focal, d = (float)dice, bo = (float)bnd, io = (float)iou;
            float total = expf(-lv[0]) * f + lv[0]
                        + expf(-lv[1]) * d + lv[1]
                        + expf(-lv[2]) * bo + lv[2]
                        + expf(-lv[3]) * io + lv[3];
            out[0] = total;
            out[1] = f;
            out[2] = d;
            out[3] = bo;
            out[4] = io;
        }
    }
    __syncthreads();
    // reset accumulator state for the next (deterministic) replay
    if (threadIdx.x < ACC_N) g_acc[threadIdx.x] = 0.0;
    if (threadIdx.x >= 128 && threadIdx.x < 128 + BB) {
        int t = threadIdx.x - 128;
        g_hasfg[t] = 0; g_hasb[t] = 0; g_anyzero[t] = 0; g_maxdi[t] = 0;
    }
}

// ---------------------------------------------------------------------------
extern "C" void kernel_launch(void* const* d_in, const int* in_sizes, int n_in,
                              void* d_out, int out_size) {
    const float* pred = (const float*)d_in[0];
    const int*   tgt  = (const int*)d_in[1];
    const float* lv   = (const float*)d_in[2];
    float* out = (float*)d_out;

    packbound_kernel<<<dim3(16, BB), 256>>>(tgt);
    dtloss_kernel<<<dim3(DT_GRID_X, BB), 256>>>(pred, lv, out);
}

// round 14
// speedup vs baseline: 19.3388x; 1.0559x over previous
#include <cuda_runtime.h>
#include <math.h>

#define HH 512
#define WW 512
#define BB 16
#define NPIX (HH*WW)
#define NTOT (BB*NPIX)
#define WPR 16            // 32-bit words per row
#define WPS (HH*WPR)      // words per sample bitmap = 8192

#define F_A  0.955f
#define F_B  1.3693f
#define BA_C (1.3693f - 0.955f)
#define F_INF 1e6f

// acc layout: 6 arrays of BB doubles
#define A_F    0
#define A_W0   16
#define A_W0D  32
#define A_I    48
#define A_P    64
#define A_T    80
#define ACC_N  96

#define DT_GRID_X 64              // 8 rows per block
#define DT_BLOCKS (DT_GRID_X * BB)

// Scratch (device globals; zero-initialized at load, self-reset each launch)
__device__ unsigned g_mbits[BB*WPS];     // mask bitmap
__device__ unsigned g_bbits[BB*WPS];     // boundary bitmap
__device__ int      g_maxdi[BB];         // per-sample max dist (float bits, >=0)
__device__ int      g_hasfg[BB];
__device__ int      g_hasb[BB];
__device__ int      g_anyzero[BB];
__device__ double   g_acc[ACC_N];
__device__ unsigned g_done;              // last-block counter (self-wrapping)

// ---------------------------------------------------------------------------
// Fused pack + boundary. Each block: sample b, 32 rows. Packs a 34-row halo
// slab into a shared bitmap, then the bitwise morphological boundary (pixel
// is boundary iff in-bounds 3x3 neighborhood, incl. self, has both 1 and 0).
__global__ void __launch_bounds__(256) packbound_kernel(const int* __restrict__ tgt) {
    int b = blockIdx.y;
    int r0 = blockIdx.x * 32;
    __shared__ unsigned pm[34 * WPR];

    for (int w = threadIdx.x; w < 34 * WPR; w += 256) {
        int ri = w >> 4;              // 0..33  -> row r0-1+ri
        int wi = w & 15;
        int y = r0 - 1 + ri;
        unsigned word = 0;
        if ((unsigned)y < (unsigned)HH) {
            const int4* T = (const int4*)(tgt + b * NPIX + y * WW + wi * 32);
            #pragma unroll
            for (int q = 0; q < 8; q++) {
                int4 v = T[q];
                word |= (v.x != 0 ? 1u : 0u) << (q*4 + 0);
                word |= (v.y != 0 ? 1u : 0u) << (q*4 + 1);
                word |= (v.z != 0 ? 1u : 0u) << (q*4 + 2);
                word |= (v.w != 0 ? 1u : 0u) << (q*4 + 3);
            }
        }
        pm[w] = word;
    }
    __syncthreads();

    int fg = 0, bd = 0, az = 0;
    #pragma unroll 1
    for (int w = threadIdx.x; w < 32 * WPR; w += 256) {
        int lr = (w >> 4) + 1;        // local row 1..32
        int wi = w & 15;
        int y = r0 + (w >> 4);
        unsigned any1 = 0, any0 = 0;
        #pragma unroll
        for (int dr = -1; dr <= 1; dr++) {
            int y2 = y + dr;
            if ((unsigned)y2 >= (unsigned)HH) continue;
            int l2 = lr + dr;
            unsigned c  = pm[l2 * WPR + wi];
            unsigned lw = (wi > 0)  ? pm[l2 * WPR + wi - 1] : 0u;
            unsigned rw = (wi < 15) ? pm[l2 * WPR + wi + 1] : 0u;
            any1 |= c | (c << 1) | (lw >> 31) | (c >> 1) | (rw << 31);
            unsigned cn = ~c;
            unsigned ln = (wi > 0)  ? ~lw : 0u;   // outside image votes nothing
            unsigned rn = (wi < 15) ? ~rw : 0u;
            any0 |= cn | (cn << 1) | (ln >> 31) | (cn >> 1) | (rn << 31);
        }
        unsigned bw = any1 & any0;
        unsigned mw = pm[lr * WPR + wi];
        g_bbits[b * WPS + y * WPR + wi] = bw;
        g_mbits[b * WPS + y * WPR + wi] = mw;
        fg |= (mw != 0u);
        bd |= (bw != 0u);
        az |= (mw != 0xffffffffu);
    }
    fg = __syncthreads_or(fg);
    bd = __syncthreads_or(bd);
    az = __syncthreads_or(az);
    if (threadIdx.x == 0) {
        if (fg) atomicOr(&g_hasfg[b], 1);
        if (bd) atomicOr(&g_hasb[b], 1);
        if (az) atomicOr(&g_anyzero[b], 1);
    }
}

// ---------------------------------------------------------------------------
// Distance (in columns) from x to nearest set bit in a 512-bit row.
// Seed word i = rw[i] ^ inv (inv selects boundary vs ~mask without staging).
__device__ __forceinline__ int nearest_bit(const unsigned* __restrict__ rw,
                                           unsigned inv, int x, int cap) {
    int wi = x >> 5, bi = x & 31;
    unsigned w = rw[wi] ^ inv;
    int d = 1 << 29;
    unsigned lm = w << (31 - bi);               // bits <= bi
    if (lm) d = __clz(lm);
    unsigned rm = w >> bi;                      // bits >= bi
    if (rm) d = min(d, __ffs(rm) - 1);
    #pragma unroll 1
    for (int k = 1; k < WPR; k++) {
        int lwi = wi - k, rwi = wi + k;
        int dl = (lwi >= 0)  ? (bi + 32*k - 31) : (1 << 29);
        int dr = (rwi < WPR) ? (32*k - bi)      : (1 << 29);
        if (min(dl, dr) >= min(d, cap)) break;
        if (lwi >= 0) {
            unsigned lw = rw[lwi] ^ inv;
            if (lw) d = min(d, bi + 32*k - 31 + __clz(lw));
        }
        if (rwi < WPR) {
            unsigned rw2 = rw[rwi] ^ inv;
            if (rw2) d = min(d, 32*k - bi + __ffs(rw2) - 1);
        }
    }
    return d;
}

// Cold path: full closed-form search when the pixel itself is not a seed.
__device__ __noinline__ float dt_search(const unsigned* __restrict__ sbase,
                                        unsigned inv, int y, int x) {
    float best = F_INF;
    int nd = nearest_bit(sbase + y * WPR, inv, x, 600);
    if (nd < (1 << 28)) best = F_A * (float)nd;
    #pragma unroll 1
    for (int dy = 1; dy < HH; dy++) {
        float ady = F_A * (float)dy;
        if (ady >= best) break;
        float capf = fmaxf((best - BA_C * (float)dy) * (1.0f / F_A),
                           fminf((float)dy, (best - ady) * (1.0f / BA_C))) + 1.0f;
        int cap = (int)fminf(capf, 600.0f);
        int yu = y - dy;
        if (yu >= 0) {
            int nd2 = nearest_bit(sbase + yu * WPR, inv, x, cap);
            if (nd2 < (1 << 28)) {
                float f = (nd2 >= dy) ? (F_A * (float)nd2 + BA_C * (float)dy)
                                      : (ady + BA_C * (float)nd2);
                best = fminf(best, f);
            }
        }
        int yd = y + dy;
        if (yd < HH) {
            int nd2 = nearest_bit(sbase + yd * WPR, inv, x, cap);
            if (nd2 < (1 << 28)) {
                float f = (nd2 >= dy) ? (F_A * (float)nd2 + BA_C * (float)dy)
                                      : (ady + BA_C * (float)nd2);
                best = fminf(best, f);
            }
        }
    }
    return best;
}

// ---------------------------------------------------------------------------
// Fused closed-form chamfer DT + loss + (last block) finalize + state reset.
// Each block: 8 rows of one sample; each thread: 4 consecutive pixels x 4 its.
// No shared bitmap staging: seed words read straight from L2-resident global
// (one word per 4 pixels on the hot path; cold dt_search is ~0.4% of pixels).
// pred uses SCALAR loads only (d_in not guaranteed 16B-aligned).
__global__ void __launch_bounds__(256) dtloss_kernel(const float* __restrict__ pred,
                                                     const float* __restrict__ lv,
                                                     float* __restrict__ out) {
    int b = blockIdx.y;
    int hb = g_hasb[b];
    const unsigned* ms = g_mbits + b * WPS;
    const unsigned* sbase = hb ? (g_bbits + b * WPS) : ms;
    const unsigned inv = hb ? 0u : 0xffffffffu;
    int hs = hb ? 1 : g_anyzero[b];

    int r0 = blockIdx.x * 8;
    float lmax = 0.0f;
    float a_f = 0.f, a_w0 = 0.f, a_w0d = 0.f, a_i = 0.f, a_p = 0.f, a_t = 0.f;

    const int x0 = (threadIdx.x & 127) * 4;
    const int ysub = threadIdx.x >> 7;       // 0 or 1

    #pragma unroll 1
    for (int it = 0; it < 4; it++) {
        int y = r0 + it * 2 + ysub;
        int wy = y * WPR + (x0 >> 5);
        unsigned sw = sbase[wy] ^ inv;
        unsigned mw = ms[wy];
        unsigned snib = (sw >> (x0 & 31)) & 0xFu;
        unsigned mnib = (mw >> (x0 & 31)) & 0xFu;
        const float* pp = pred + b * NPIX + y * WW + x0;
        float xs0 = pp[0], xs1 = pp[1], xs2 = pp[2], xs3 = pp[3];

        #pragma unroll
        for (int k = 0; k < 4; k++) {
            float best;
            if ((snib >> k) & 1u)      best = 0.0f;          // pixel is a seed
            else if (hs)               best = dt_search(sbase, inv, y, x0 + k);
            else                       best = F_INF;
            lmax = fmaxf(lmax, best);

            int tb = (mnib >> k) & 1u;
            float xv = (k == 0) ? xs0 : (k == 1) ? xs1 : (k == 2) ? xs2 : xs3;
            // u = tb ? -x : x ; om = sigmoid(u) ; bce = softplus(u)
            float u = tb ? -xv : xv;
            float e = __expf(-fabsf(xv));
            float r = __fdividef(1.0f, 1.0f + e);
            float om = (u >= 0.0f) ? r : 1.0f - r;
            float bce = fmaxf(u, 0.0f) + __logf(1.0f + e);
            float p = tb ? 1.0f - om : om;                    // sigmoid(x)
            float at = tb ? 0.25f : 0.75f;
            a_f   += at * om * om * bce;
            a_w0  += om;
            a_w0d += om * best;
            if (tb) { a_i += p; a_t += 1.0f; }
            a_p += p;
        }
    }

    // block reduce 6 sums + max
    #pragma unroll
    for (int o = 16; o > 0; o >>= 1) {
        a_f   += __shfl_down_sync(0xffffffffu, a_f,   o);
        a_w0  += __shfl_down_sync(0xffffffffu, a_w0,  o);
        a_w0d += __shfl_down_sync(0xffffffffu, a_w0d, o);
        a_i   += __shfl_down_sync(0xffffffffu, a_i,   o);
        a_p   += __shfl_down_sync(0xffffffffu, a_p,   o);
        a_t   += __shfl_down_sync(0xffffffffu, a_t,   o);
        lmax   = fmaxf(lmax, __shfl_down_sync(0xffffffffu, lmax, o));
    }
    __shared__ float red[8][7];
    int lane = threadIdx.x & 31, wid = threadIdx.x >> 5;
    if (lane == 0) {
        red[wid][0] = a_f;  red[wid][1] = a_w0; red[wid][2] = a_w0d;
        red[wid][3] = a_i;  red[wid][4] = a_p;  red[wid][5] = a_t;
        red[wid][6] = lmax;
    }
    __syncthreads();
    if (threadIdx.x == 0) {
        float s0=0, s1=0, s2=0, s3=0, s4=0, s5=0, m6=0;
        #pragma unroll
        for (int w = 0; w < 8; w++) {
            s0 += red[w][0]; s1 += red[w][1]; s2 += red[w][2];
            s3 += red[w][3]; s4 += red[w][4]; s5 += red[w][5];
            m6 = fmaxf(m6, red[w][6]);
        }
        atomicAdd(&g_acc[A_F + b],   (double)s0);
        atomicAdd(&g_acc[A_W0 + b],  (double)s1);
        atomicAdd(&g_acc[A_W0D + b], (double)s2);
        atomicAdd(&g_acc[A_I + b],   (double)s3);
        atomicAdd(&g_acc[A_P + b],   (double)s4);
        atomicAdd(&g_acc[A_T + b],   (double)s5);
        atomicMax(&g_maxdi[b], __float_as_int(m6));   // valid: m6 >= 0
    }

    // ---- last-block finalize (threadfence reduction idiom) ----
    __shared__ int isLast;
    __threadfence();
    if (threadIdx.x == 0) {
        unsigned n = atomicInc(&g_done, DT_BLOCKS - 1);   // wraps to 0 on last
        isLast = (n == DT_BLOCKS - 1);
    }
    __syncthreads();
    if (!isLast) return;

    // One warp: lane b (0..15) handles sample b; parallel loads hide latency.
    if (wid == 0) {
        double f_b = 0.0, bnd_b = 0.0, dice_b = 0.0, iou_b = 0.0;
        if (lane < BB) {
            int bb2 = lane;
            f_b = g_acc[A_F + bb2];
            double w0s  = g_acc[A_W0 + bb2];
            double w0ds = g_acc[A_W0D + bb2];
            if (g_hasfg[bb2]) {
                float mx = __int_as_float(g_maxdi[bb2]);
                double scale = (mx > 0.0f) ? 1.0 / fmax((double)mx, 1e-12) : 1.0;
                bnd_b = w0s + scale * w0ds;   // sum w0*(1 + d/mx)
            } else {
                bnd_b = 2.0 * w0s;            // dist == 1 everywhere
            }
            double inter = g_acc[A_I + bb2];
            double tot = g_acc[A_P + bb2] + g_acc[A_T + bb2];
            dice_b = (2.0 * inter + 1e-6) / (tot + 1e-6);
            iou_b  = (inter + 1e-6) / (tot - inter + 1e-6);
        }
        #pragma unroll
        for (int o = 8; o > 0; o >>= 1) {
            f_b    += __shfl_down_sync(0xffffffffu, f_b,    o);
            bnd_b  += __shfl_down_sync(0xffffffffu, bnd_b,  o);
            dice_b += __shfl_down_sync(0xffffffffu, dice_b, o);
            iou_b  += __shfl_down_sync(0xffffffffu, iou_b,  o);
        }
        if (lane == 0) {
            double N = (double)NTOT;
            double focal = f_b / N;
            double bnd   = bnd_b / N;
            double dice  = 1.0 - dice_b / (double)BB;
            double iou   = 1.0 - iou_b / (double)BB;
            float f = (float)focal, d = (float)dice, bo = (float)bnd, io = (float)iou;
            float total = expf(-lv[0]) * f + lv[0]
                        + expf(-lv[1]) * d + lv[1]
                        + expf(-lv[2]) * bo + lv[2]
                        + expf(-lv[3]) * io + lv[3];
            out[0] = total;
            out[1] = f;
            out[2] = d;
            out[3] = bo;
            out[4] = io;
        }
    }
    __syncthreads();
    // reset accumulator state for the next (deterministic) replay
    if (threadIdx.x < ACC_N) g_acc[threadIdx.x] = 0.0;
    if (threadIdx.x >= 128 && threadIdx.x < 128 + BB) {
        int t = threadIdx.x - 128;
        g_hasfg[t] = 0; g_hasb[t] = 0; g_anyzero[t] = 0; g_maxdi[t] = 0;
    }
}

// ---------------------------------------------------------------------------
extern "C" void kernel_launch(void* const* d_in, const int* in_sizes, int n_in,
                              void* d_out, int out_size) {
    const float* pred = (const float*)d_in[0];
    const int*   tgt  = (const int*)d_in[1];
    const float* lv   = (const float*)d_in[2];
    float* out = (float*)d_out;

    packbound_kernel<<<dim3(16, BB), 256>>>(tgt);
    dtloss_kernel<<<dim3(DT_GRID_X, BB), 256>>>(pred, lv, out);
}